// round 1
// baseline (speedup 1.0000x reference)
#include <cuda_runtime.h>
#include <math.h>

// Problem constants
#define B_   2
#define S_   2048
#define H_   2048
#define NH_  16
#define HD_  128
#define MTOT (B_ * S_)          // 4096 rows for projection GEMMs

// ---------------------------------------------------------------------------
// Device scratch (no cudaMalloc allowed). ~128 MB total.
// Q,K,V stored as [B][NH][S][HD] for attention; attn as [B][S][H] for out-proj.
// ---------------------------------------------------------------------------
__device__ float g_q[(size_t)B_ * NH_ * S_ * HD_];
__device__ float g_k[(size_t)B_ * NH_ * S_ * HD_];
__device__ float g_v[(size_t)B_ * NH_ * S_ * HD_];
__device__ float g_attn[(size_t)B_ * S_ * H_];

// ---------------------------------------------------------------------------
// SGEMM with bias: C = A(MxK) @ Bm(KxN) + bias(N)
// BM=BN=128, BK=8, TM=TN=8, 256 threads.
// SCATTER=true writes C into [B][NH][S][HD] layout (for Q/K/V proj).
// ---------------------------------------------------------------------------
template <bool SCATTER>
__global__ __launch_bounds__(256)
void sgemm_bias(const float* __restrict__ A, const float* __restrict__ Bm,
                const float* __restrict__ bias, float* __restrict__ C,
                int M, int N, int K)
{
    constexpr int BM = 128, BN = 128, BK = 8, TM = 8, TN = 8;
    __shared__ float As[BK][BM];
    __shared__ float Bs[BK][BN];

    const int tid = threadIdx.x;
    const int tr  = tid >> 4;        // 0..15
    const int tc  = tid & 15;        // 0..15
    const int mBase = blockIdx.y * BM;
    const int nBase = blockIdx.x * BN;

    const float* Ag = A + (size_t)mBase * K;
    const float* Bg = Bm + nBase;

    const int aRow = tid >> 1;         // 0..127
    const int aCol = (tid & 1) * 4;    // 0 or 4
    const int bRow = tid >> 5;         // 0..7
    const int bCol = (tid & 31) * 4;   // 0..124

    float acc[TM][TN] = {};
    float regM[TM], regN[TN];

    for (int k0 = 0; k0 < K; k0 += BK) {
        float4 a4 = *(const float4*)(Ag + (size_t)aRow * K + k0 + aCol);
        As[aCol + 0][aRow] = a4.x;
        As[aCol + 1][aRow] = a4.y;
        As[aCol + 2][aRow] = a4.z;
        As[aCol + 3][aRow] = a4.w;
        *(float4*)(&Bs[bRow][bCol]) =
            *(const float4*)(Bg + (size_t)(k0 + bRow) * N + bCol);
        __syncthreads();

        #pragma unroll
        for (int k = 0; k < BK; k++) {
            *(float4*)&regM[0] = *(float4*)&As[k][tr * TM];
            *(float4*)&regM[4] = *(float4*)&As[k][tr * TM + 4];
            *(float4*)&regN[0] = *(float4*)&Bs[k][tc * TN];
            *(float4*)&regN[4] = *(float4*)&Bs[k][tc * TN + 4];
            #pragma unroll
            for (int i = 0; i < TM; i++)
                #pragma unroll
                for (int j = 0; j < TN; j++)
                    acc[i][j] += regM[i] * regN[j];
        }
        __syncthreads();
    }

    // Epilogue: bias + store (optionally scattered into [B][NH][S][HD])
    #pragma unroll
    for (int i = 0; i < TM; i++) {
        const int m = mBase + tr * TM + i;
        #pragma unroll
        for (int j = 0; j < TN; j += 4) {
            const int n = nBase + tc * TN + j;
            float4 r;
            r.x = acc[i][j + 0] + bias[n + 0];
            r.y = acc[i][j + 1] + bias[n + 1];
            r.z = acc[i][j + 2] + bias[n + 2];
            r.w = acc[i][j + 3] + bias[n + 3];
            if (SCATTER) {
                const int b = m >> 11;        // m / S_
                const int s = m & (S_ - 1);
                const int h = n >> 7;         // n / HD_
                const int d = n & (HD_ - 1);
                const size_t idx = (((size_t)(b * NH_ + h)) * S_ + s) * HD_ + d;
                *(float4*)&C[idx] = r;
            } else {
                *(float4*)&C[(size_t)m * N + n] = r;
            }
        }
    }
}

// ---------------------------------------------------------------------------
// Flash-style attention, fp32.
// grid: (S/64, B*NH). block: 256 threads. Each CTA: 64 q-rows x HD=128.
// Streams K/V in 64-row tiles with online softmax.
// ---------------------------------------------------------------------------
#define BQ  64
#define BKT 64

__global__ __launch_bounds__(256)
void attn_kernel(const float* __restrict__ Q, const float* __restrict__ Kt,
                 const float* __restrict__ V, const float* __restrict__ mask,
                 float* __restrict__ out)
{
    extern __shared__ float sm[];
    float* Qs = sm;                     // 64*128
    float* Ks = Qs + BQ * HD_;          // 64*128
    float* Vs = Ks + BKT * HD_;         // 64*128
    float* Ps = Vs + BKT * HD_;         // 64*64
    float* Ms = Ps + BQ * BKT;          // 64

    const int bh = blockIdx.y;          // b*NH + h
    const int b  = bh / NH_;
    const int h  = bh % NH_;
    const int q0 = blockIdx.x * BQ;
    const int tid = threadIdx.x;
    const int tr  = tid >> 4;           // 0..15  (4 q-rows each)
    const int tc  = tid & 15;           // 0..15

    const float* Qg = Q + ((size_t)bh * S_ + q0) * HD_;
    const float* Kg = Kt + (size_t)bh * S_ * HD_;
    const float* Vg = V + (size_t)bh * S_ * HD_;

    // Load Q tile (coalesced float4)
    #pragma unroll
    for (int it = 0; it < 8; it++) {
        const int lin = it * 256 + tid;
        const int row = lin >> 5;
        const int c4  = (lin & 31) << 2;
        *(float4*)&Qs[row * HD_ + c4] = *(const float4*)&Qg[(size_t)row * HD_ + c4];
    }

    float m_i[4], l_i[4], O[4][8];
    #pragma unroll
    for (int i = 0; i < 4; i++) {
        m_i[i] = -1e30f;
        l_i[i] = 0.f;
        #pragma unroll
        for (int j = 0; j < 8; j++) O[i][j] = 0.f;
    }

    const float scale = 0.08838834764831845f;   // 1/sqrt(128)

    for (int kt = 0; kt < S_ / BKT; kt++) {
        const int k0 = kt * BKT;
        __syncthreads();   // all threads done with Ks/Vs/Ps from prev iter

        #pragma unroll
        for (int it = 0; it < 8; it++) {
            const int lin = it * 256 + tid;
            const int row = lin >> 5;
            const int c4  = (lin & 31) << 2;
            *(float4*)&Ks[row * HD_ + c4] =
                *(const float4*)&Kg[(size_t)(k0 + row) * HD_ + c4];
            *(float4*)&Vs[row * HD_ + c4] =
                *(const float4*)&Vg[(size_t)(k0 + row) * HD_ + c4];
        }
        if (tid < BKT) Ms[tid] = mask[(size_t)b * S_ + k0 + tid];
        __syncthreads();

        // ---- S tile = Q @ K^T (4x4 per thread) ----
        float acc[4][4] = {};
        #pragma unroll 8
        for (int kk = 0; kk < HD_; kk += 4) {
            float4 q4[4], k4[4];
            #pragma unroll
            for (int i = 0; i < 4; i++)
                q4[i] = *(float4*)&Qs[(tr * 4 + i) * HD_ + kk];
            #pragma unroll
            for (int j = 0; j < 4; j++)
                k4[j] = *(float4*)&Ks[(tc * 4 + j) * HD_ + kk];
            #pragma unroll
            for (int i = 0; i < 4; i++)
                #pragma unroll
                for (int j = 0; j < 4; j++)
                    acc[i][j] += q4[i].x * k4[j].x + q4[i].y * k4[j].y +
                                 q4[i].z * k4[j].z + q4[i].w * k4[j].w;
        }

        // ---- scale + mask + online softmax (rows spread over 16 lanes) ----
        #pragma unroll
        for (int i = 0; i < 4; i++) {
            float s[4];
            float rm = -1e30f;
            #pragma unroll
            for (int j = 0; j < 4; j++) {
                s[j] = acc[i][j] * scale + Ms[tc * 4 + j];
                rm = fmaxf(rm, s[j]);
            }
            #pragma unroll
            for (int o = 8; o > 0; o >>= 1)
                rm = fmaxf(rm, __shfl_xor_sync(0xffffffffu, rm, o));

            const float mn = fmaxf(m_i[i], rm);
            const float alpha = __expf(m_i[i] - mn);
            float rs = 0.f;
            float p[4];
            #pragma unroll
            for (int j = 0; j < 4; j++) {
                p[j] = __expf(s[j] - mn);
                rs += p[j];
            }
            #pragma unroll
            for (int o = 8; o > 0; o >>= 1)
                rs += __shfl_xor_sync(0xffffffffu, rs, o);

            l_i[i] = l_i[i] * alpha + rs;
            m_i[i] = mn;
            #pragma unroll
            for (int j = 0; j < 8; j++) O[i][j] *= alpha;

            float4 pv = make_float4(p[0], p[1], p[2], p[3]);
            *(float4*)&Ps[(tr * 4 + i) * BKT + tc * 4] = pv;
        }
        __syncthreads();

        // ---- O += P @ V (4 rows x 8 cols per thread) ----
        #pragma unroll 4
        for (int kk = 0; kk < BKT; kk++) {
            const float4 v0 = *(float4*)&Vs[kk * HD_ + tc * 8];
            const float4 v1 = *(float4*)&Vs[kk * HD_ + tc * 8 + 4];
            #pragma unroll
            for (int i = 0; i < 4; i++) {
                const float pr = Ps[(tr * 4 + i) * BKT + kk];
                O[i][0] += pr * v0.x;  O[i][1] += pr * v0.y;
                O[i][2] += pr * v0.z;  O[i][3] += pr * v0.w;
                O[i][4] += pr * v1.x;  O[i][5] += pr * v1.y;
                O[i][6] += pr * v1.z;  O[i][7] += pr * v1.w;
            }
        }
    }

    // ---- finalize: divide by l, write [B][S][H] ----
    #pragma unroll
    for (int i = 0; i < 4; i++) {
        const float inv = 1.f / l_i[i];
        const int q = q0 + tr * 4 + i;
        float* dst = out + ((size_t)b * S_ + q) * H_ + h * HD_ + tc * 8;
        float4 o0 = make_float4(O[i][0] * inv, O[i][1] * inv,
                                O[i][2] * inv, O[i][3] * inv);
        float4 o1 = make_float4(O[i][4] * inv, O[i][5] * inv,
                                O[i][6] * inv, O[i][7] * inv);
        *(float4*)dst       = o0;
        *(float4*)(dst + 4) = o1;
    }
}

// ---------------------------------------------------------------------------
// Launch
// ---------------------------------------------------------------------------
extern "C" void kernel_launch(void* const* d_in, const int* in_sizes, int n_in,
                              void* d_out, int out_size)
{
    const float* x    = (const float*)d_in[0];
    const float* mask = (const float*)d_in[1];
    const float* Wq   = (const float*)d_in[2];
    const float* bq   = (const float*)d_in[3];
    const float* Wk   = (const float*)d_in[4];
    const float* bk   = (const float*)d_in[5];
    const float* Wv   = (const float*)d_in[6];
    const float* bv   = (const float*)d_in[7];
    const float* Wo   = (const float*)d_in[8];
    const float* bo   = (const float*)d_in[9];
    float* out = (float*)d_out;

    float *q, *k, *v, *attn;
    cudaGetSymbolAddress((void**)&q,    g_q);
    cudaGetSymbolAddress((void**)&k,    g_k);
    cudaGetSymbolAddress((void**)&v,    g_v);
    cudaGetSymbolAddress((void**)&attn, g_attn);

    dim3 ggrid(H_ / 128, MTOT / 128);   // (16, 32)

    sgemm_bias<true><<<ggrid, 256>>>(x, Wq, bq, q, MTOT, H_, H_);
    sgemm_bias<true><<<ggrid, 256>>>(x, Wk, bk, k, MTOT, H_, H_);
    sgemm_bias<true><<<ggrid, 256>>>(x, Wv, bv, v, MTOT, H_, H_);

    const size_t smem = (size_t)(3 * BQ * HD_ + BQ * BKT + BKT) * sizeof(float);
    cudaFuncSetAttribute(attn_kernel,
                         cudaFuncAttributeMaxDynamicSharedMemorySize, (int)smem);
    attn_kernel<<<dim3(S_ / BQ, B_ * NH_), 256, smem>>>(q, k, v, mask, attn);

    sgemm_bias<false><<<ggrid, 256>>>(attn, Wo, bo, out, MTOT, H_, H_);
}

// round 2
// speedup vs baseline: 4.8798x; 4.8798x over previous
#include <cuda_runtime.h>
#include <math.h>
#include <stdint.h>

// Problem constants
#define B_   2
#define S_   2048
#define H_   2048
#define NH_  16
#define HD_  128
#define MTOT (B_ * S_)          // 4096 rows for projection GEMMs

// ---------------------------------------------------------------------------
// Device scratch
// ---------------------------------------------------------------------------
__device__ float g_q[(size_t)B_ * NH_ * S_ * HD_];
__device__ float g_k[(size_t)B_ * NH_ * S_ * HD_];
__device__ float g_v[(size_t)B_ * NH_ * S_ * HD_];
__device__ float g_attn[(size_t)B_ * S_ * H_];

// ---------------------------------------------------------------------------
// Helpers
// ---------------------------------------------------------------------------
__device__ __forceinline__ uint32_t cvt_tf32(float f) {
    uint32_t u;
    asm("cvt.rna.tf32.f32 %0, %1;" : "=r"(u) : "f"(f));
    return u;
}

__device__ __forceinline__ void cp16(void* s, const void* g) {
    uint32_t sa = (uint32_t)__cvta_generic_to_shared(s);
    asm volatile("cp.async.cg.shared.global [%0], [%1], 16;" :: "r"(sa), "l"(g));
}
__device__ __forceinline__ void cp_commit() {
    asm volatile("cp.async.commit_group;");
}
__device__ __forceinline__ void cp_wait1() {
    asm volatile("cp.async.wait_group 1;");
}
__device__ __forceinline__ void cp_wait0() {
    asm volatile("cp.async.wait_group 0;");
}

// m16n8k8 TF32 mma. Fragment layouts (g=lane>>2, t4=lane&3):
//   A: a0=(g,t4) a1=(g+8,t4) a2=(g,t4+4) a3=(g+8,t4+4)   [row, k]
//   B: b0=(k=t4, n=g) b1=(k=t4+4, n=g)
//   C: c0=(g,2t4) c1=(g,2t4+1) c2=(g+8,2t4) c3=(g+8,2t4+1)
__device__ __forceinline__ void mma_tf32(float (&c)[4], const uint32_t (&a)[4],
                                         const uint32_t (&b)[2]) {
    asm volatile(
        "mma.sync.aligned.m16n8k8.row.col.f32.tf32.tf32.f32 "
        "{%0,%1,%2,%3}, {%4,%5,%6,%7}, {%8,%9}, {%0,%1,%2,%3};\n"
        : "+f"(c[0]), "+f"(c[1]), "+f"(c[2]), "+f"(c[3])
        : "r"(a[0]), "r"(a[1]), "r"(a[2]), "r"(a[3]), "r"(b[0]), "r"(b[1]));
}

// ---------------------------------------------------------------------------
// TF32 tensor-core GEMM: C = A(MxK) @ W(KxN) + bias
// BM=BN=128, BK=32, 8 warps (2x4), warp tile 64x32, cp.async double buffer.
// Smem strides: A 36 (36%32==4 -> conflict-free A-frag lds),
//               B 136 (136%32==8 -> conflict-free B-frag lds).
// ---------------------------------------------------------------------------
#define G_ASTR 36
#define G_BSTR 136
#define G_SMEM ((2 * 128 * G_ASTR + 2 * 32 * G_BSTR) * 4)   // 71680 B

template <bool SCATTER>
__global__ __launch_bounds__(256, 2)
void gemm_tf32(const float* __restrict__ A, const float* __restrict__ W,
               const float* __restrict__ bias, float* __restrict__ C,
               int M, int N, int K)
{
    constexpr int BM = 128, BN = 128, BK = 32;
    extern __shared__ float sm[];
    float* As = sm;                       // 2 x 128 x 36
    float* Bs = sm + 2 * BM * G_ASTR;     // 2 x 32 x 136

    const int tid = threadIdx.x;
    const int w = tid >> 5, lane = tid & 31, g = lane >> 2, t4 = lane & 3;
    const int wr = w >> 2, wc = w & 3;          // warp grid 2x4
    const int mBase = blockIdx.y * BM;
    const int nBase = blockIdx.x * BN;

    float acc[4][4][4] = {};

    auto loadTiles = [&](int k0, int buf) {
        float* Ab = As + buf * BM * G_ASTR;
        float* Bb = Bs + buf * BK * G_BSTR;
        #pragma unroll
        for (int i = 0; i < 4; i++) {
            int id = tid + i * 256;
            int r = id >> 3, c4 = (id & 7) * 4;
            cp16(Ab + r * G_ASTR + c4, A + (size_t)(mBase + r) * K + k0 + c4);
        }
        #pragma unroll
        for (int i = 0; i < 4; i++) {
            int id = tid + i * 256;
            int r = id >> 5, c4 = (id & 31) * 4;
            cp16(Bb + r * G_BSTR + c4, W + (size_t)(k0 + r) * N + nBase + c4);
        }
        cp_commit();
    };

    loadTiles(0, 0);
    const int nIter = K / BK;   // 64

    for (int kt = 0; kt < nIter; kt++) {
        if (kt + 1 < nIter) { loadTiles((kt + 1) * BK, (kt + 1) & 1); cp_wait1(); }
        else                { cp_wait0(); }
        __syncthreads();

        const float* Ab = As + (kt & 1) * BM * G_ASTR;
        const float* Bb = Bs + (kt & 1) * BK * G_BSTR;

        #pragma unroll
        for (int k8 = 0; k8 < 4; k8++) {
            uint32_t af[4][4], bf[4][2];
            #pragma unroll
            for (int mi = 0; mi < 4; mi++) {
                const float* p = Ab + (wr * 64 + mi * 16 + g) * G_ASTR + k8 * 8 + t4;
                af[mi][0] = cvt_tf32(p[0]);
                af[mi][1] = cvt_tf32(p[8 * G_ASTR]);
                af[mi][2] = cvt_tf32(p[4]);
                af[mi][3] = cvt_tf32(p[8 * G_ASTR + 4]);
            }
            #pragma unroll
            for (int ni = 0; ni < 4; ni++) {
                const float* p = Bb + (k8 * 8 + t4) * G_BSTR + wc * 32 + ni * 8 + g;
                bf[ni][0] = cvt_tf32(p[0]);
                bf[ni][1] = cvt_tf32(p[4 * G_BSTR]);
            }
            #pragma unroll
            for (int mi = 0; mi < 4; mi++)
                #pragma unroll
                for (int ni = 0; ni < 4; ni++)
                    mma_tf32(acc[mi][ni], af[mi], bf[ni]);
        }
        __syncthreads();
    }

    // Epilogue: bias + store (optionally scattered into [B][NH][S][HD])
    #pragma unroll
    for (int mi = 0; mi < 4; mi++) {
        #pragma unroll
        for (int r2 = 0; r2 < 2; r2++) {
            const int m = mBase + wr * 64 + mi * 16 + g + r2 * 8;
            #pragma unroll
            for (int ni = 0; ni < 4; ni++) {
                const int n = nBase + wc * 32 + ni * 8 + 2 * t4;
                float2 v;
                v.x = acc[mi][ni][r2 * 2 + 0] + bias[n];
                v.y = acc[mi][ni][r2 * 2 + 1] + bias[n + 1];
                if (SCATTER) {
                    const int b = m >> 11;
                    const int s = m & (S_ - 1);
                    const int h = n >> 7;
                    const int d = n & (HD_ - 1);
                    *(float2*)&C[(((size_t)(b * NH_ + h)) * S_ + s) * HD_ + d] = v;
                } else {
                    *(float2*)&C[(size_t)m * N + n] = v;
                }
            }
        }
    }
}

// ---------------------------------------------------------------------------
// TF32 flash attention.
// grid (S/128, B*NH), 256 threads (8 warps as 4 row-groups x 2 halves).
// BQ=128, BKT=32, HD=128. K/V cp.async double-buffered.
// S phase: warp tile M=32 x N=16 (wc = K-col half).
// PV phase: warp tile M=32 x N=64 (wc = HD half).
// ---------------------------------------------------------------------------
#define AT_BQ  128
#define AT_BK  32
#define QSTR   132
#define KSTR   132
#define VSTR   136
#define PSTR   36
#define AT_SMEM ((AT_BQ*QSTR + 2*AT_BK*KSTR + 2*AT_BK*VSTR + AT_BQ*PSTR + \
                  2*AT_BQ + 2*AT_BQ + 2*AT_BK) * 4)      // 156928 B

__global__ __launch_bounds__(256, 1)
void attn_tf32(const float* __restrict__ Q, const float* __restrict__ K,
               const float* __restrict__ V, const float* __restrict__ mask,
               float* __restrict__ out)
{
    extern __shared__ float sm[];
    float* Qs   = sm;                         // 128 x 132
    float* Ks   = Qs + AT_BQ * QSTR;          // 2 x 32 x 132
    float* Vs   = Ks + 2 * AT_BK * KSTR;      // 2 x 32 x 136
    float* Ps   = Vs + 2 * AT_BK * VSTR;      // 128 x 36
    float* rmax = Ps + AT_BQ * PSTR;          // 2 x 128
    float* rsum = rmax + 2 * AT_BQ;           // 2 x 128
    float* msk  = rsum + 2 * AT_BQ;           // 2 x 32

    const int tid = threadIdx.x;
    const int w = tid >> 5, lane = tid & 31, g = lane >> 2, t4 = lane & 3;
    const int wr = w >> 1, wc = w & 1;
    const int bh = blockIdx.y;
    const int b  = bh >> 4;                   // bh / NH_
    const int q0 = blockIdx.x * AT_BQ;

    const float* Qg = Q + ((size_t)bh * S_ + q0) * HD_;
    const float* Kg = K + (size_t)bh * S_ * HD_;
    const float* Vg = V + (size_t)bh * S_ * HD_;
    const float* maskg = mask + (size_t)b * S_;

    // Q tile (once)
    #pragma unroll
    for (int i = 0; i < 16; i++) {
        int id = tid + i * 256;
        int r = id >> 5, c4 = (id & 31) * 4;
        cp16(Qs + r * QSTR + c4, Qg + (size_t)r * HD_ + c4);
    }
    cp_commit();

    auto loadKV = [&](int kb, int buf) {
        float* Kb = Ks + buf * AT_BK * KSTR;
        float* Vb = Vs + buf * AT_BK * VSTR;
        #pragma unroll
        for (int i = 0; i < 4; i++) {
            int id = tid + i * 256;
            int r = id >> 5, c4 = (id & 31) * 4;
            cp16(Kb + r * KSTR + c4, Kg + (size_t)(kb + r) * HD_ + c4);
            cp16(Vb + r * VSTR + c4, Vg + (size_t)(kb + r) * HD_ + c4);
        }
        if (tid < AT_BK) msk[buf * AT_BK + tid] = maskg[kb + tid];
        cp_commit();
    };

    loadKV(0, 0);

    float O[2][8][4];
    float m_i[2][2], l_i[2][2];
    #pragma unroll
    for (int mi = 0; mi < 2; mi++) {
        m_i[mi][0] = -1e30f; m_i[mi][1] = -1e30f;
        l_i[mi][0] = 0.f;    l_i[mi][1] = 0.f;
        #pragma unroll
        for (int nt = 0; nt < 8; nt++)
            #pragma unroll
            for (int c = 0; c < 4; c++) O[mi][nt][c] = 0.f;
    }

    const float scale = 0.08838834764831845f;   // 1/sqrt(128)
    const int nIter = S_ / AT_BK;               // 64

    for (int kt = 0; kt < nIter; kt++) {
        if (kt + 1 < nIter) { loadKV((kt + 1) * AT_BK, (kt + 1) & 1); cp_wait1(); }
        else                { cp_wait0(); }
        __syncthreads();                                         // S1

        const float* Kb = Ks + (kt & 1) * AT_BK * KSTR;
        const float* Vb = Vs + (kt & 1) * AT_BK * VSTR;
        const float* mk = msk + (kt & 1) * AT_BK;

        // ---- S = Q @ K^T ----
        float sacc[2][2][4] = {};
        #pragma unroll
        for (int k8 = 0; k8 < 16; k8++) {
            uint32_t af[2][4], bf[2][2];
            #pragma unroll
            for (int mi = 0; mi < 2; mi++) {
                const float* p = Qs + (wr * 32 + mi * 16 + g) * QSTR + k8 * 8 + t4;
                af[mi][0] = cvt_tf32(p[0]);
                af[mi][1] = cvt_tf32(p[8 * QSTR]);
                af[mi][2] = cvt_tf32(p[4]);
                af[mi][3] = cvt_tf32(p[8 * QSTR + 4]);
            }
            #pragma unroll
            for (int ni = 0; ni < 2; ni++) {
                const float* p = Kb + (wc * 16 + ni * 8 + g) * KSTR + k8 * 8 + t4;
                bf[ni][0] = cvt_tf32(p[0]);
                bf[ni][1] = cvt_tf32(p[4]);
            }
            #pragma unroll
            for (int mi = 0; mi < 2; mi++)
                #pragma unroll
                for (int ni = 0; ni < 2; ni++)
                    mma_tf32(sacc[mi][ni], af[mi], bf[ni]);
        }

        // scale + mask
        #pragma unroll
        for (int mi = 0; mi < 2; mi++)
            #pragma unroll
            for (int ni = 0; ni < 2; ni++)
                #pragma unroll
                for (int c = 0; c < 4; c++) {
                    const int col = wc * 16 + ni * 8 + 2 * t4 + (c & 1);
                    sacc[mi][ni][c] = sacc[mi][ni][c] * scale + mk[col];
                }

        // partial row max (this warp's 16 cols), quad-reduced
        #pragma unroll
        for (int mi = 0; mi < 2; mi++)
            #pragma unroll
            for (int r2 = 0; r2 < 2; r2++) {
                float v = fmaxf(fmaxf(sacc[mi][0][r2 * 2], sacc[mi][0][r2 * 2 + 1]),
                                fmaxf(sacc[mi][1][r2 * 2], sacc[mi][1][r2 * 2 + 1]));
                v = fmaxf(v, __shfl_xor_sync(0xffffffffu, v, 1));
                v = fmaxf(v, __shfl_xor_sync(0xffffffffu, v, 2));
                if (t4 == 0)
                    rmax[wc * AT_BQ + wr * 32 + mi * 16 + g + r2 * 8] = v;
            }
        __syncthreads();                                         // S2

        float alpha[2][2];
        #pragma unroll
        for (int mi = 0; mi < 2; mi++)
            #pragma unroll
            for (int r2 = 0; r2 < 2; r2++) {
                const int row = wr * 32 + mi * 16 + g + r2 * 8;
                const float rm = fmaxf(rmax[row], rmax[AT_BQ + row]);
                const float mn = fmaxf(m_i[mi][r2], rm);
                alpha[mi][r2] = __expf(m_i[mi][r2] - mn);
                m_i[mi][r2] = mn;

                float p0 = __expf(sacc[mi][0][r2 * 2]     - mn);
                float p1 = __expf(sacc[mi][0][r2 * 2 + 1] - mn);
                float p2 = __expf(sacc[mi][1][r2 * 2]     - mn);
                float p3 = __expf(sacc[mi][1][r2 * 2 + 1] - mn);

                float s = p0 + p1 + p2 + p3;
                s += __shfl_xor_sync(0xffffffffu, s, 1);
                s += __shfl_xor_sync(0xffffffffu, s, 2);
                if (t4 == 0) rsum[wc * AT_BQ + row] = s;

                float* pp = Ps + row * PSTR + wc * 16;
                *(float2*)&pp[2 * t4]     = make_float2(p0, p1);
                *(float2*)&pp[8 + 2 * t4] = make_float2(p2, p3);
            }
        __syncthreads();                                         // S3

        #pragma unroll
        for (int mi = 0; mi < 2; mi++)
            #pragma unroll
            for (int r2 = 0; r2 < 2; r2++) {
                const int row = wr * 32 + mi * 16 + g + r2 * 8;
                const float rs = rsum[row] + rsum[AT_BQ + row];
                const float a = alpha[mi][r2];
                l_i[mi][r2] = l_i[mi][r2] * a + rs;
                #pragma unroll
                for (int nt = 0; nt < 8; nt++) {
                    O[mi][nt][r2 * 2]     *= a;
                    O[mi][nt][r2 * 2 + 1] *= a;
                }
            }

        // ---- O += P @ V ----
        #pragma unroll
        for (int k8 = 0; k8 < 4; k8++) {
            uint32_t af[2][4], bf[8][2];
            #pragma unroll
            for (int mi = 0; mi < 2; mi++) {
                const float* p = Ps + (wr * 32 + mi * 16 + g) * PSTR + k8 * 8 + t4;
                af[mi][0] = cvt_tf32(p[0]);
                af[mi][1] = cvt_tf32(p[8 * PSTR]);
                af[mi][2] = cvt_tf32(p[4]);
                af[mi][3] = cvt_tf32(p[8 * PSTR + 4]);
            }
            #pragma unroll
            for (int nt = 0; nt < 8; nt++) {
                const float* p = Vb + (k8 * 8 + t4) * VSTR + wc * 64 + nt * 8 + g;
                bf[nt][0] = cvt_tf32(p[0]);
                bf[nt][1] = cvt_tf32(p[4 * VSTR]);
            }
            #pragma unroll
            for (int mi = 0; mi < 2; mi++)
                #pragma unroll
                for (int nt = 0; nt < 8; nt++)
                    mma_tf32(O[mi][nt], af[mi], bf[nt]);
        }
        __syncthreads();                                         // S4
    }

    // finalize: divide by l, write [B][S][H]
    const int h = bh & (NH_ - 1);
    #pragma unroll
    for (int mi = 0; mi < 2; mi++)
        #pragma unroll
        for (int r2 = 0; r2 < 2; r2++) {
            const float inv = 1.f / l_i[mi][r2];
            const int q = q0 + wr * 32 + mi * 16 + g + r2 * 8;
            float* dst = out + ((size_t)b * S_ + q) * H_ + h * HD_;
            #pragma unroll
            for (int nt = 0; nt < 8; nt++) {
                const int col = wc * 64 + nt * 8 + 2 * t4;
                float2 v = make_float2(O[mi][nt][r2 * 2] * inv,
                                       O[mi][nt][r2 * 2 + 1] * inv);
                *(float2*)&dst[col] = v;
            }
        }
}

// ---------------------------------------------------------------------------
// Launch
// ---------------------------------------------------------------------------
extern "C" void kernel_launch(void* const* d_in, const int* in_sizes, int n_in,
                              void* d_out, int out_size)
{
    const float* x    = (const float*)d_in[0];
    const float* mask = (const float*)d_in[1];
    const float* Wq   = (const float*)d_in[2];
    const float* bq   = (const float*)d_in[3];
    const float* Wk   = (const float*)d_in[4];
    const float* bk   = (const float*)d_in[5];
    const float* Wv   = (const float*)d_in[6];
    const float* bv   = (const float*)d_in[7];
    const float* Wo   = (const float*)d_in[8];
    const float* bo   = (const float*)d_in[9];
    float* out = (float*)d_out;

    float *q, *k, *v, *attn;
    cudaGetSymbolAddress((void**)&q,    g_q);
    cudaGetSymbolAddress((void**)&k,    g_k);
    cudaGetSymbolAddress((void**)&v,    g_v);
    cudaGetSymbolAddress((void**)&attn, g_attn);

    cudaFuncSetAttribute(gemm_tf32<true>,
                         cudaFuncAttributeMaxDynamicSharedMemorySize, G_SMEM);
    cudaFuncSetAttribute(gemm_tf32<false>,
                         cudaFuncAttributeMaxDynamicSharedMemorySize, G_SMEM);
    cudaFuncSetAttribute(attn_tf32,
                         cudaFuncAttributeMaxDynamicSharedMemorySize, AT_SMEM);

    dim3 ggrid(H_ / 128, MTOT / 128);   // (16, 32)

    gemm_tf32<true><<<ggrid, 256, G_SMEM>>>(x, Wq, bq, q, MTOT, H_, H_);
    gemm_tf32<true><<<ggrid, 256, G_SMEM>>>(x, Wk, bk, k, MTOT, H_, H_);
    gemm_tf32<true><<<ggrid, 256, G_SMEM>>>(x, Wv, bv, v, MTOT, H_, H_);

    attn_tf32<<<dim3(S_ / AT_BQ, B_ * NH_), 256, AT_SMEM>>>(q, k, v, mask, attn);

    gemm_tf32<false><<<ggrid, 256, G_SMEM>>>(attn, Wo, bo, out, MTOT, H_, H_);
}

// round 3
// speedup vs baseline: 5.1757x; 1.0606x over previous
#include <cuda_runtime.h>
#include <math.h>
#include <stdint.h>

// Problem constants
#define B_   2
#define S_   2048
#define H_   2048
#define NH_  16
#define HD_  128
#define MTOT (B_ * S_)          // 4096 rows for projection GEMMs

// ---------------------------------------------------------------------------
// Device scratch
// ---------------------------------------------------------------------------
__device__ float g_q[(size_t)B_ * NH_ * S_ * HD_];
__device__ float g_k[(size_t)B_ * NH_ * S_ * HD_];
__device__ float g_v[(size_t)B_ * NH_ * S_ * HD_];
__device__ float g_attn[(size_t)B_ * S_ * H_];
__device__ float g_xt[(size_t)MTOT * H_];          // tf32-rounded x
__device__ float g_wt[(size_t)4 * H_ * H_];        // tf32-rounded Wq,Wk,Wv,Wo

// ---------------------------------------------------------------------------
// Helpers
// ---------------------------------------------------------------------------
__device__ __forceinline__ uint32_t cvt_tf32(float f) {
    uint32_t u;
    asm("cvt.rna.tf32.f32 %0, %1;" : "=r"(u) : "f"(f));
    return u;
}
__device__ __forceinline__ float round_tf32(float f) {
    return __uint_as_float(cvt_tf32(f));
}

__device__ __forceinline__ void cp16(void* s, const void* g) {
    uint32_t sa = (uint32_t)__cvta_generic_to_shared(s);
    asm volatile("cp.async.cg.shared.global [%0], [%1], 16;" :: "r"(sa), "l"(g));
}
__device__ __forceinline__ void cp_commit() {
    asm volatile("cp.async.commit_group;");
}
__device__ __forceinline__ void cp_wait0() {
    asm volatile("cp.async.wait_group 0;");
}

// m16n8k8 TF32 mma. Fragment layouts (g=lane>>2, t4=lane&3):
//   A: a0=(g,t4) a1=(g+8,t4) a2=(g,t4+4) a3=(g+8,t4+4)   [row, k]
//   B: b0=(k=t4, n=g) b1=(k=t4+4, n=g)
//   C: c0=(g,2t4) c1=(g,2t4+1) c2=(g+8,2t4) c3=(g+8,2t4+1)
__device__ __forceinline__ void mma_tf32(float (&c)[4], const uint32_t (&a)[4],
                                         const uint32_t (&b)[2]) {
    asm volatile(
        "mma.sync.aligned.m16n8k8.row.col.f32.tf32.tf32.f32 "
        "{%0,%1,%2,%3}, {%4,%5,%6,%7}, {%8,%9}, {%0,%1,%2,%3};\n"
        : "+f"(c[0]), "+f"(c[1]), "+f"(c[2]), "+f"(c[3])
        : "r"(a[0]), "r"(a[1]), "r"(a[2]), "r"(a[3]), "r"(b[0]), "r"(b[1]));
}

// ---------------------------------------------------------------------------
// Elementwise tf32 pre-rounding (bandwidth-bound, ~30us total)
// ---------------------------------------------------------------------------
__global__ void roundcast(const float* __restrict__ src, float* __restrict__ dst,
                          int n4)
{
    int i = blockIdx.x * blockDim.x + threadIdx.x;
    if (i < n4) {
        float4 v = ((const float4*)src)[i];
        v.x = round_tf32(v.x);
        v.y = round_tf32(v.y);
        v.z = round_tf32(v.z);
        v.w = round_tf32(v.w);
        ((float4*)dst)[i] = v;
    }
}

// ---------------------------------------------------------------------------
// TF32 tensor-core GEMM: C = A(MxK) @ W(KxN) + bias
// Inputs already tf32-rounded; no cvt anywhere in the loop.
// BM=BN=128, BK=32, 8 warps (2x4), warp tile 64x32, cp.async double buffer,
// one __syncthreads per K-iter.
// SCATTER=true: output rounded to tf32 and scattered to [B][NH][S][HD].
// ---------------------------------------------------------------------------
#define G_ASTR 36
#define G_BSTR 136
#define G_SMEM ((2 * 128 * G_ASTR + 2 * 32 * G_BSTR) * 4)   // 71680 B

template <bool SCATTER>
__global__ __launch_bounds__(256, 2)
void gemm_tf32(const float* __restrict__ A, const float* __restrict__ W,
               const float* __restrict__ bias, float* __restrict__ C,
               int M, int N, int K)
{
    constexpr int BM = 128, BN = 128, BK = 32;
    extern __shared__ float sm[];
    float* As = sm;                       // 2 x 128 x 36
    float* Bs = sm + 2 * BM * G_ASTR;     // 2 x 32 x 136

    const int tid = threadIdx.x;
    const int w = tid >> 5, lane = tid & 31, g = lane >> 2, t4 = lane & 3;
    const int wr = w >> 2, wc = w & 3;          // warp grid 2x4
    const int mBase = blockIdx.y * BM;
    const int nBase = blockIdx.x * BN;

    float acc[4][4][4] = {};

    auto loadTiles = [&](int k0, int buf) {
        float* Ab = As + buf * BM * G_ASTR;
        float* Bb = Bs + buf * BK * G_BSTR;
        #pragma unroll
        for (int i = 0; i < 4; i++) {
            int id = tid + i * 256;
            int r = id >> 3, c4 = (id & 7) * 4;
            cp16(Ab + r * G_ASTR + c4, A + (size_t)(mBase + r) * K + k0 + c4);
        }
        #pragma unroll
        for (int i = 0; i < 4; i++) {
            int id = tid + i * 256;
            int r = id >> 5, c4 = (id & 31) * 4;
            cp16(Bb + r * G_BSTR + c4, W + (size_t)(k0 + r) * N + nBase + c4);
        }
        cp_commit();
    };

    loadTiles(0, 0);
    const int nIter = K / BK;   // 64

    for (int kt = 0; kt < nIter; kt++) {
        cp_wait0();
        __syncthreads();
        if (kt + 1 < nIter) loadTiles((kt + 1) * BK, (kt + 1) & 1);

        const float* Ab = As + (kt & 1) * BM * G_ASTR;
        const float* Bb = Bs + (kt & 1) * BK * G_BSTR;

        #pragma unroll
        for (int k8 = 0; k8 < 4; k8++) {
            uint32_t af[4][4], bf[4][2];
            #pragma unroll
            for (int mi = 0; mi < 4; mi++) {
                const float* p = Ab + (wr * 64 + mi * 16 + g) * G_ASTR + k8 * 8 + t4;
                af[mi][0] = __float_as_uint(p[0]);
                af[mi][1] = __float_as_uint(p[8 * G_ASTR]);
                af[mi][2] = __float_as_uint(p[4]);
                af[mi][3] = __float_as_uint(p[8 * G_ASTR + 4]);
            }
            #pragma unroll
            for (int ni = 0; ni < 4; ni++) {
                const float* p = Bb + (k8 * 8 + t4) * G_BSTR + wc * 32 + ni * 8 + g;
                bf[ni][0] = __float_as_uint(p[0]);
                bf[ni][1] = __float_as_uint(p[4 * G_BSTR]);
            }
            #pragma unroll
            for (int mi = 0; mi < 4; mi++)
                #pragma unroll
                for (int ni = 0; ni < 4; ni++)
                    mma_tf32(acc[mi][ni], af[mi], bf[ni]);
        }
    }

    // Epilogue: bias + store
    #pragma unroll
    for (int mi = 0; mi < 4; mi++) {
        #pragma unroll
        for (int r2 = 0; r2 < 2; r2++) {
            const int m = mBase + wr * 64 + mi * 16 + g + r2 * 8;
            #pragma unroll
            for (int ni = 0; ni < 4; ni++) {
                const int n = nBase + wc * 32 + ni * 8 + 2 * t4;
                float2 v;
                v.x = acc[mi][ni][r2 * 2 + 0] + bias[n];
                v.y = acc[mi][ni][r2 * 2 + 1] + bias[n + 1];
                if (SCATTER) {
                    v.x = round_tf32(v.x);
                    v.y = round_tf32(v.y);
                    const int b = m >> 11;
                    const int s = m & (S_ - 1);
                    const int h = n >> 7;
                    const int d = n & (HD_ - 1);
                    *(float2*)&C[(((size_t)(b * NH_ + h)) * S_ + s) * HD_ + d] = v;
                } else {
                    *(float2*)&C[(size_t)m * N + n] = v;
                }
            }
        }
    }
}

// ---------------------------------------------------------------------------
// TF32 flash attention. Q/K/V already tf32-rounded; P rounded at smem write;
// output rounded for the downstream out-projection.
// grid (S/128, B*NH), 256 threads (8 warps as 4 row-groups x 2 halves).
// 3 __syncthreads per K-tile.
// ---------------------------------------------------------------------------
#define AT_BQ  128
#define AT_BK  32
#define QSTR   132
#define KSTR   132
#define VSTR   136
#define PSTR   36
#define AT_SMEM ((AT_BQ*QSTR + 2*AT_BK*KSTR + 2*AT_BK*VSTR + AT_BQ*PSTR + \
                  2*AT_BQ + 2*AT_BQ + 2*AT_BK) * 4)      // 156928 B

__global__ __launch_bounds__(256, 1)
void attn_tf32(const float* __restrict__ Q, const float* __restrict__ K,
               const float* __restrict__ V, const float* __restrict__ mask,
               float* __restrict__ out)
{
    extern __shared__ float sm[];
    float* Qs   = sm;                         // 128 x 132
    float* Ks   = Qs + AT_BQ * QSTR;          // 2 x 32 x 132
    float* Vs   = Ks + 2 * AT_BK * KSTR;      // 2 x 32 x 136
    float* Ps   = Vs + 2 * AT_BK * VSTR;      // 128 x 36
    float* rmax = Ps + AT_BQ * PSTR;          // 2 x 128
    float* rsum = rmax + 2 * AT_BQ;           // 2 x 128
    float* msk  = rsum + 2 * AT_BQ;           // 2 x 32

    const int tid = threadIdx.x;
    const int w = tid >> 5, lane = tid & 31, g = lane >> 2, t4 = lane & 3;
    const int wr = w >> 1, wc = w & 1;
    const int bh = blockIdx.y;
    const int b  = bh >> 4;                   // bh / NH_
    const int q0 = blockIdx.x * AT_BQ;

    const float* Qg = Q + ((size_t)bh * S_ + q0) * HD_;
    const float* Kg = K + (size_t)bh * S_ * HD_;
    const float* Vg = V + (size_t)bh * S_ * HD_;
    const float* maskg = mask + (size_t)b * S_;

    // Q tile (once)
    #pragma unroll
    for (int i = 0; i < 16; i++) {
        int id = tid + i * 256;
        int r = id >> 5, c4 = (id & 31) * 4;
        cp16(Qs + r * QSTR + c4, Qg + (size_t)r * HD_ + c4);
    }
    cp_commit();

    auto loadKV = [&](int kb, int buf) {
        float* Kb = Ks + buf * AT_BK * KSTR;
        float* Vb = Vs + buf * AT_BK * VSTR;
        #pragma unroll
        for (int i = 0; i < 4; i++) {
            int id = tid + i * 256;
            int r = id >> 5, c4 = (id & 31) * 4;
            cp16(Kb + r * KSTR + c4, Kg + (size_t)(kb + r) * HD_ + c4);
            cp16(Vb + r * VSTR + c4, Vg + (size_t)(kb + r) * HD_ + c4);
        }
        if (tid < AT_BK) msk[buf * AT_BK + tid] = maskg[kb + tid];
        cp_commit();
    };

    loadKV(0, 0);

    float O[2][8][4];
    float m_i[2][2], l_i[2][2];
    #pragma unroll
    for (int mi = 0; mi < 2; mi++) {
        m_i[mi][0] = -1e30f; m_i[mi][1] = -1e30f;
        l_i[mi][0] = 0.f;    l_i[mi][1] = 0.f;
        #pragma unroll
        for (int nt = 0; nt < 8; nt++)
            #pragma unroll
            for (int c = 0; c < 4; c++) O[mi][nt][c] = 0.f;
    }

    const float scale = 0.08838834764831845f;   // 1/sqrt(128)
    const int nIter = S_ / AT_BK;               // 64

    for (int kt = 0; kt < nIter; kt++) {
        cp_wait0();
        __syncthreads();                                         // S1
        if (kt + 1 < nIter) loadKV((kt + 1) * AT_BK, (kt + 1) & 1);

        const float* Kb = Ks + (kt & 1) * AT_BK * KSTR;
        const float* Vb = Vs + (kt & 1) * AT_BK * VSTR;
        const float* mk = msk + (kt & 1) * AT_BK;

        // ---- S = Q @ K^T ----
        float sacc[2][2][4] = {};
        #pragma unroll
        for (int k8 = 0; k8 < 16; k8++) {
            uint32_t af[2][4], bf[2][2];
            #pragma unroll
            for (int mi = 0; mi < 2; mi++) {
                const float* p = Qs + (wr * 32 + mi * 16 + g) * QSTR + k8 * 8 + t4;
                af[mi][0] = __float_as_uint(p[0]);
                af[mi][1] = __float_as_uint(p[8 * QSTR]);
                af[mi][2] = __float_as_uint(p[4]);
                af[mi][3] = __float_as_uint(p[8 * QSTR + 4]);
            }
            #pragma unroll
            for (int ni = 0; ni < 2; ni++) {
                const float* p = Kb + (wc * 16 + ni * 8 + g) * KSTR + k8 * 8 + t4;
                bf[ni][0] = __float_as_uint(p[0]);
                bf[ni][1] = __float_as_uint(p[4]);
            }
            #pragma unroll
            for (int mi = 0; mi < 2; mi++)
                #pragma unroll
                for (int ni = 0; ni < 2; ni++)
                    mma_tf32(sacc[mi][ni], af[mi], bf[ni]);
        }

        // scale + mask
        #pragma unroll
        for (int mi = 0; mi < 2; mi++)
            #pragma unroll
            for (int ni = 0; ni < 2; ni++)
                #pragma unroll
                for (int c = 0; c < 4; c++) {
                    const int col = wc * 16 + ni * 8 + 2 * t4 + (c & 1);
                    sacc[mi][ni][c] = sacc[mi][ni][c] * scale + mk[col];
                }

        // partial row max (this warp's 16 cols), quad-reduced
        #pragma unroll
        for (int mi = 0; mi < 2; mi++)
            #pragma unroll
            for (int r2 = 0; r2 < 2; r2++) {
                float v = fmaxf(fmaxf(sacc[mi][0][r2 * 2], sacc[mi][0][r2 * 2 + 1]),
                                fmaxf(sacc[mi][1][r2 * 2], sacc[mi][1][r2 * 2 + 1]));
                v = fmaxf(v, __shfl_xor_sync(0xffffffffu, v, 1));
                v = fmaxf(v, __shfl_xor_sync(0xffffffffu, v, 2));
                if (t4 == 0)
                    rmax[wc * AT_BQ + wr * 32 + mi * 16 + g + r2 * 8] = v;
            }
        __syncthreads();                                         // S2

        float alpha[2][2];
        #pragma unroll
        for (int mi = 0; mi < 2; mi++)
            #pragma unroll
            for (int r2 = 0; r2 < 2; r2++) {
                const int row = wr * 32 + mi * 16 + g + r2 * 8;
                const float rm = fmaxf(rmax[row], rmax[AT_BQ + row]);
                const float mn = fmaxf(m_i[mi][r2], rm);
                alpha[mi][r2] = __expf(m_i[mi][r2] - mn);
                m_i[mi][r2] = mn;

                float p0 = __expf(sacc[mi][0][r2 * 2]     - mn);
                float p1 = __expf(sacc[mi][0][r2 * 2 + 1] - mn);
                float p2 = __expf(sacc[mi][1][r2 * 2]     - mn);
                float p3 = __expf(sacc[mi][1][r2 * 2 + 1] - mn);

                float s = p0 + p1 + p2 + p3;
                s += __shfl_xor_sync(0xffffffffu, s, 1);
                s += __shfl_xor_sync(0xffffffffu, s, 2);
                if (t4 == 0) rsum[wc * AT_BQ + row] = s;

                float* pp = Ps + row * PSTR + wc * 16;
                *(float2*)&pp[2 * t4] =
                    make_float2(round_tf32(p0), round_tf32(p1));
                *(float2*)&pp[8 + 2 * t4] =
                    make_float2(round_tf32(p2), round_tf32(p3));
            }
        __syncthreads();                                         // S3

        #pragma unroll
        for (int mi = 0; mi < 2; mi++)
            #pragma unroll
            for (int r2 = 0; r2 < 2; r2++) {
                const int row = wr * 32 + mi * 16 + g + r2 * 8;
                const float rs = rsum[row] + rsum[AT_BQ + row];
                const float a = alpha[mi][r2];
                l_i[mi][r2] = l_i[mi][r2] * a + rs;
                #pragma unroll
                for (int nt = 0; nt < 8; nt++) {
                    O[mi][nt][r2 * 2]     *= a;
                    O[mi][nt][r2 * 2 + 1] *= a;
                }
            }

        // ---- O += P @ V ----
        #pragma unroll
        for (int k8 = 0; k8 < 4; k8++) {
            uint32_t af[2][4], bf[8][2];
            #pragma unroll
            for (int mi = 0; mi < 2; mi++) {
                const float* p = Ps + (wr * 32 + mi * 16 + g) * PSTR + k8 * 8 + t4;
                af[mi][0] = __float_as_uint(p[0]);
                af[mi][1] = __float_as_uint(p[8 * PSTR]);
                af[mi][2] = __float_as_uint(p[4]);
                af[mi][3] = __float_as_uint(p[8 * PSTR + 4]);
            }
            #pragma unroll
            for (int nt = 0; nt < 8; nt++) {
                const float* p = Vb + (k8 * 8 + t4) * VSTR + wc * 64 + nt * 8 + g;
                bf[nt][0] = __float_as_uint(p[0]);
                bf[nt][1] = __float_as_uint(p[4 * VSTR]);
            }
            #pragma unroll
            for (int mi = 0; mi < 2; mi++)
                #pragma unroll
                for (int nt = 0; nt < 8; nt++)
                    mma_tf32(O[mi][nt], af[mi], bf[nt]);
        }
    }

    // finalize: divide by l, round to tf32 for out-projection, write [B][S][H]
    const int h = bh & (NH_ - 1);
    #pragma unroll
    for (int mi = 0; mi < 2; mi++)
        #pragma unroll
        for (int r2 = 0; r2 < 2; r2++) {
            const float inv = 1.f / l_i[mi][r2];
            const int q = q0 + wr * 32 + mi * 16 + g + r2 * 8;
            float* dst = out + ((size_t)b * S_ + q) * H_ + h * HD_;
            #pragma unroll
            for (int nt = 0; nt < 8; nt++) {
                const int col = wc * 64 + nt * 8 + 2 * t4;
                float2 v = make_float2(round_tf32(O[mi][nt][r2 * 2] * inv),
                                       round_tf32(O[mi][nt][r2 * 2 + 1] * inv));
                *(float2*)&dst[col] = v;
            }
        }
}

// ---------------------------------------------------------------------------
// Launch
// ---------------------------------------------------------------------------
extern "C" void kernel_launch(void* const* d_in, const int* in_sizes, int n_in,
                              void* d_out, int out_size)
{
    const float* x    = (const float*)d_in[0];
    const float* mask = (const float*)d_in[1];
    const float* Wq   = (const float*)d_in[2];
    const float* bq   = (const float*)d_in[3];
    const float* Wk   = (const float*)d_in[4];
    const float* bk   = (const float*)d_in[5];
    const float* Wv   = (const float*)d_in[6];
    const float* bv   = (const float*)d_in[7];
    const float* Wo   = (const float*)d_in[8];
    const float* bo   = (const float*)d_in[9];
    float* out = (float*)d_out;

    float *q, *k, *v, *attn, *xt, *wt;
    cudaGetSymbolAddress((void**)&q,    g_q);
    cudaGetSymbolAddress((void**)&k,    g_k);
    cudaGetSymbolAddress((void**)&v,    g_v);
    cudaGetSymbolAddress((void**)&attn, g_attn);
    cudaGetSymbolAddress((void**)&xt,   g_xt);
    cudaGetSymbolAddress((void**)&wt,   g_wt);

    cudaFuncSetAttribute(gemm_tf32<true>,
                         cudaFuncAttributeMaxDynamicSharedMemorySize, G_SMEM);
    cudaFuncSetAttribute(gemm_tf32<false>,
                         cudaFuncAttributeMaxDynamicSharedMemorySize, G_SMEM);
    cudaFuncSetAttribute(attn_tf32,
                         cudaFuncAttributeMaxDynamicSharedMemorySize, AT_SMEM);

    // Pre-round inputs/weights to tf32 (removes all cvt from GEMM hot loops)
    const int nx4 = MTOT * H_ / 4;          // 2,097,152
    const int nw4 = H_ * H_ / 4;            // 1,048,576
    const size_t wsz = (size_t)H_ * H_;
    roundcast<<<(nx4 + 255) / 256, 256>>>(x,  xt,            nx4);
    roundcast<<<(nw4 + 255) / 256, 256>>>(Wq, wt + 0 * wsz, nw4);
    roundcast<<<(nw4 + 255) / 256, 256>>>(Wk, wt + 1 * wsz, nw4);
    roundcast<<<(nw4 + 255) / 256, 256>>>(Wv, wt + 2 * wsz, nw4);
    roundcast<<<(nw4 + 255) / 256, 256>>>(Wo, wt + 3 * wsz, nw4);

    dim3 ggrid(H_ / 128, MTOT / 128);   // (16, 32)

    gemm_tf32<true><<<ggrid, 256, G_SMEM>>>(xt, wt + 0 * wsz, bq, q, MTOT, H_, H_);
    gemm_tf32<true><<<ggrid, 256, G_SMEM>>>(xt, wt + 1 * wsz, bk, k, MTOT, H_, H_);
    gemm_tf32<true><<<ggrid, 256, G_SMEM>>>(xt, wt + 2 * wsz, bv, v, MTOT, H_, H_);

    attn_tf32<<<dim3(S_ / AT_BQ, B_ * NH_), 256, AT_SMEM>>>(q, k, v, mask, attn);

    gemm_tf32<false><<<ggrid, 256, G_SMEM>>>(attn, wt + 3 * wsz, bo, out, MTOT, H_, H_);
}

// round 5
// speedup vs baseline: 5.3732x; 1.0381x over previous
#include <cuda_runtime.h>
#include <math.h>
#include <stdint.h>

// Problem constants
#define B_   2
#define S_   2048
#define H_   2048
#define NH_  16
#define HD_  128
#define MTOT (B_ * S_)          // 4096 rows for projection GEMMs

// ---------------------------------------------------------------------------
// Device scratch
// ---------------------------------------------------------------------------
__device__ float g_q[(size_t)B_ * NH_ * S_ * HD_];
__device__ float g_k[(size_t)B_ * NH_ * S_ * HD_];
__device__ float g_v[(size_t)B_ * NH_ * S_ * HD_];
__device__ float g_attn[(size_t)B_ * S_ * H_];
__device__ float g_xt[(size_t)MTOT * H_];          // tf32-rounded x
__device__ float g_wt[(size_t)4 * H_ * H_];        // tf32-rounded Wq,Wk,Wv,Wo

// ---------------------------------------------------------------------------
// Helpers
// ---------------------------------------------------------------------------
__device__ __forceinline__ uint32_t cvt_tf32(float f) {
    uint32_t u;
    asm("cvt.rna.tf32.f32 %0, %1;" : "=r"(u) : "f"(f));
    return u;
}
__device__ __forceinline__ float round_tf32(float f) {
    return __uint_as_float(cvt_tf32(f));
}
__device__ __forceinline__ void cp16(void* s, const void* g) {
    uint32_t sa = (uint32_t)__cvta_generic_to_shared(s);
    asm volatile("cp.async.cg.shared.global [%0], [%1], 16;" :: "r"(sa), "l"(g));
}
__device__ __forceinline__ void cp_commit() {
    asm volatile("cp.async.commit_group;");
}
__device__ __forceinline__ void cp_wait0() {
    asm volatile("cp.async.wait_group 0;");
}

// m16n8k8 TF32 mma. Fragment layouts (g=lane>>2, t4=lane&3):
//   A: a0=(g,t4) a1=(g+8,t4) a2=(g,t4+4) a3=(g+8,t4+4)   [row, k]
//   B: b0=(k=t4, n=g) b1=(k=t4+4, n=g)
//   C: c0=(g,2t4) c1=(g,2t4+1) c2=(g+8,2t4) c3=(g+8,2t4+1)
__device__ __forceinline__ void mma_tf32(float (&c)[4], const uint32_t (&a)[4],
                                         const uint32_t (&b)[2]) {
    asm volatile(
        "mma.sync.aligned.m16n8k8.row.col.f32.tf32.tf32.f32 "
        "{%0,%1,%2,%3}, {%4,%5,%6,%7}, {%8,%9}, {%0,%1,%2,%3};\n"
        : "+f"(c[0]), "+f"(c[1]), "+f"(c[2]), "+f"(c[3])
        : "r"(a[0]), "r"(a[1]), "r"(a[2]), "r"(a[3]), "r"(b[0]), "r"(b[1]));
}

// ---------------------------------------------------------------------------
// Elementwise tf32 pre-rounding
// ---------------------------------------------------------------------------
__global__ void roundcast(const float* __restrict__ src, float* __restrict__ dst,
                          int n4)
{
    int i = blockIdx.x * blockDim.x + threadIdx.x;
    if (i < n4) {
        float4 v = ((const float4*)src)[i];
        v.x = round_tf32(v.x);
        v.y = round_tf32(v.y);
        v.z = round_tf32(v.z);
        v.w = round_tf32(v.w);
        ((float4*)dst)[i] = v;
    }
}

// ---------------------------------------------------------------------------
// TF32 tensor-core GEMM (known-good from Round 3): C = A(MxK) @ W(KxN) + bias
// ---------------------------------------------------------------------------
#define G_ASTR 36
#define G_BSTR 136
#define G_SMEM ((2 * 128 * G_ASTR + 2 * 32 * G_BSTR) * 4)   // 71680 B

template <bool SCATTER>
__global__ __launch_bounds__(256, 2)
void gemm_tf32(const float* __restrict__ A, const float* __restrict__ W,
               const float* __restrict__ bias, float* __restrict__ C,
               int M, int N, int K)
{
    constexpr int BM = 128, BN = 128, BK = 32;
    extern __shared__ float sm[];
    float* As = sm;                       // 2 x 128 x 36
    float* Bs = sm + 2 * BM * G_ASTR;     // 2 x 32 x 136

    const int tid = threadIdx.x;
    const int w = tid >> 5, lane = tid & 31, g = lane >> 2, t4 = lane & 3;
    const int wr = w >> 2, wc = w & 3;          // warp grid 2x4
    const int mBase = blockIdx.y * BM;
    const int nBase = blockIdx.x * BN;

    float acc[4][4][4] = {};

    auto loadTiles = [&](int k0, int buf) {
        float* Ab = As + buf * BM * G_ASTR;
        float* Bb = Bs + buf * BK * G_BSTR;
        #pragma unroll
        for (int i = 0; i < 4; i++) {
            int id = tid + i * 256;
            int r = id >> 3, c4 = (id & 7) * 4;
            cp16(Ab + r * G_ASTR + c4, A + (size_t)(mBase + r) * K + k0 + c4);
        }
        #pragma unroll
        for (int i = 0; i < 4; i++) {
            int id = tid + i * 256;
            int r = id >> 5, c4 = (id & 31) * 4;
            cp16(Bb + r * G_BSTR + c4, W + (size_t)(k0 + r) * N + nBase + c4);
        }
        cp_commit();
    };

    loadTiles(0, 0);
    const int nIter = K / BK;   // 64

    for (int kt = 0; kt < nIter; kt++) {
        cp_wait0();
        __syncthreads();
        if (kt + 1 < nIter) loadTiles((kt + 1) * BK, (kt + 1) & 1);

        const float* Ab = As + (kt & 1) * BM * G_ASTR;
        const float* Bb = Bs + (kt & 1) * BK * G_BSTR;

        #pragma unroll
        for (int k8 = 0; k8 < 4; k8++) {
            uint32_t af[4][4], bf[4][2];
            #pragma unroll
            for (int mi = 0; mi < 4; mi++) {
                const float* p = Ab + (wr * 64 + mi * 16 + g) * G_ASTR + k8 * 8 + t4;
                af[mi][0] = __float_as_uint(p[0]);
                af[mi][1] = __float_as_uint(p[8 * G_ASTR]);
                af[mi][2] = __float_as_uint(p[4]);
                af[mi][3] = __float_as_uint(p[8 * G_ASTR + 4]);
            }
            #pragma unroll
            for (int ni = 0; ni < 4; ni++) {
                const float* p = Bb + (k8 * 8 + t4) * G_BSTR + wc * 32 + ni * 8 + g;
                bf[ni][0] = __float_as_uint(p[0]);
                bf[ni][1] = __float_as_uint(p[4 * G_BSTR]);
            }
            #pragma unroll
            for (int mi = 0; mi < 4; mi++)
                #pragma unroll
                for (int ni = 0; ni < 4; ni++)
                    mma_tf32(acc[mi][ni], af[mi], bf[ni]);
        }
    }

    #pragma unroll
    for (int mi = 0; mi < 4; mi++) {
        #pragma unroll
        for (int r2 = 0; r2 < 2; r2++) {
            const int m = mBase + wr * 64 + mi * 16 + g + r2 * 8;
            #pragma unroll
            for (int ni = 0; ni < 4; ni++) {
                const int n = nBase + wc * 32 + ni * 8 + 2 * t4;
                float2 v;
                v.x = acc[mi][ni][r2 * 2 + 0] + bias[n];
                v.y = acc[mi][ni][r2 * 2 + 1] + bias[n + 1];
                if (SCATTER) {
                    v.x = round_tf32(v.x);
                    v.y = round_tf32(v.y);
                    const int b = m >> 11;
                    const int s = m & (S_ - 1);
                    const int h = n >> 7;
                    const int d = n & (HD_ - 1);
                    *(float2*)&C[(((size_t)(b * NH_ + h)) * S_ + s) * HD_ + d] = v;
                } else {
                    *(float2*)&C[(size_t)m * N + n] = v;
                }
            }
        }
    }
}

// ---------------------------------------------------------------------------
// TF32 flash attention v2: decoupled warps.
// 256 threads, 8 warps; warp w owns rows w*16..w*16+15 (BQ=128), FULL N=32
// and FULL d=128. In-warp softmax (quad shuffles). P re-fragmented from the
// S accumulator into PV A-fragments via shuffles (no Ps smem, no extra syncs).
// Single-buffered K/V (2 CTAs/SM hide the load latency). 2 syncs/iter.
// ---------------------------------------------------------------------------
#define AT_BQ  128
#define AT_BK  32
#define QSTR   132
#define KSTR   132
#define VSTR   136
#define AT_SMEM ((AT_BQ*QSTR + AT_BK*KSTR + AT_BK*VSTR + AT_BK) * 4)  // 102016 B

__global__ __launch_bounds__(256, 2)
void attn_tf32(const float* __restrict__ Q, const float* __restrict__ K,
               const float* __restrict__ V, const float* __restrict__ mask,
               float* __restrict__ out)
{
    extern __shared__ float sm[];
    float* Qs  = sm;                       // 128 x 132
    float* Ks  = Qs + AT_BQ * QSTR;        // 32 x 132
    float* Vs  = Ks + AT_BK * KSTR;        // 32 x 136
    float* msk = Vs + AT_BK * VSTR;        // 32

    const int tid = threadIdx.x;
    const int w = tid >> 5, lane = tid & 31, g = lane >> 2, t4 = lane & 3;
    const int bh = blockIdx.y;
    const int b  = bh >> 4;                // bh / NH_
    const int q0 = blockIdx.x * AT_BQ;

    const float* Qg = Q + ((size_t)bh * S_ + q0) * HD_;
    const float* Kg = K + (size_t)bh * S_ * HD_;
    const float* Vg = V + (size_t)bh * S_ * HD_;
    const float* maskg = mask + (size_t)b * S_;

    // Q tile (once)
    #pragma unroll
    for (int i = 0; i < 16; i++) {
        int id = tid + i * 256;
        int r = id >> 5, c4 = (id & 31) * 4;
        cp16(Qs + r * QSTR + c4, Qg + (size_t)r * HD_ + c4);
    }
    auto loadKV = [&](int kb0) {
        #pragma unroll
        for (int i = 0; i < 4; i++) {
            int id = tid + i * 256;
            int r = id >> 5, c4 = (id & 31) * 4;
            cp16(Ks + r * KSTR + c4, Kg + (size_t)(kb0 + r) * HD_ + c4);
            cp16(Vs + r * VSTR + c4, Vg + (size_t)(kb0 + r) * HD_ + c4);
        }
        if (tid < AT_BK) msk[tid] = maskg[kb0 + tid];
    };
    loadKV(0);
    cp_commit();
    cp_wait0();
    __syncthreads();

    float O[16][4];
    #pragma unroll
    for (int nt = 0; nt < 16; nt++)
        #pragma unroll
        for (int c = 0; c < 4; c++) O[nt][c] = 0.f;
    float m_lo = -1e30f, m_hi = -1e30f, l_lo = 0.f, l_hi = 0.f;

    const float scale = 0.08838834764831845f;   // 1/sqrt(128)
    const int nIter = S_ / AT_BK;               // 64
    const int rowA = w * 16 + g;                // lo row in Q tile

    for (int kt = 0; kt < nIter; kt++) {
        // ---- S = Q @ K^T  (16 x 32 per warp) ----
        float sacc[4][4] = {};
        #pragma unroll
        for (int k8 = 0; k8 < 16; k8++) {
            uint32_t af[4];
            const float* qp = Qs + rowA * QSTR + k8 * 8 + t4;
            af[0] = __float_as_uint(qp[0]);
            af[1] = __float_as_uint(qp[8 * QSTR]);
            af[2] = __float_as_uint(qp[4]);
            af[3] = __float_as_uint(qp[8 * QSTR + 4]);
            #pragma unroll
            for (int ni = 0; ni < 4; ni++) {
                uint32_t bf[2];
                const float* kp = Ks + (ni * 8 + g) * KSTR + k8 * 8 + t4;
                bf[0] = __float_as_uint(kp[0]);
                bf[1] = __float_as_uint(kp[4]);
                mma_tf32(sacc[ni], af, bf);
            }
        }

        // ---- scale + mask ----
        #pragma unroll
        for (int ni = 0; ni < 4; ni++)
            #pragma unroll
            for (int c = 0; c < 4; c++) {
                const int col = ni * 8 + 2 * t4 + (c & 1);
                sacc[ni][c] = sacc[ni][c] * scale + msk[col];
            }

        // ---- in-warp softmax (rows g and g+8; quad reduce over t4) ----
        float rm_lo = -1e30f, rm_hi = -1e30f;
        #pragma unroll
        for (int ni = 0; ni < 4; ni++) {
            rm_lo = fmaxf(rm_lo, fmaxf(sacc[ni][0], sacc[ni][1]));
            rm_hi = fmaxf(rm_hi, fmaxf(sacc[ni][2], sacc[ni][3]));
        }
        rm_lo = fmaxf(rm_lo, __shfl_xor_sync(0xffffffffu, rm_lo, 1));
        rm_lo = fmaxf(rm_lo, __shfl_xor_sync(0xffffffffu, rm_lo, 2));
        rm_hi = fmaxf(rm_hi, __shfl_xor_sync(0xffffffffu, rm_hi, 1));
        rm_hi = fmaxf(rm_hi, __shfl_xor_sync(0xffffffffu, rm_hi, 2));

        const float mn_lo = fmaxf(m_lo, rm_lo);
        const float mn_hi = fmaxf(m_hi, rm_hi);
        const float al_lo = __expf(m_lo - mn_lo);
        const float al_hi = __expf(m_hi - mn_hi);
        m_lo = mn_lo;
        m_hi = mn_hi;

        float sum_lo = 0.f, sum_hi = 0.f;
        #pragma unroll
        for (int ni = 0; ni < 4; ni++) {
            float p0 = __expf(sacc[ni][0] - mn_lo);
            float p1 = __expf(sacc[ni][1] - mn_lo);
            float p2 = __expf(sacc[ni][2] - mn_hi);
            float p3 = __expf(sacc[ni][3] - mn_hi);
            sum_lo += p0 + p1;
            sum_hi += p2 + p3;
            sacc[ni][0] = round_tf32(p0);
            sacc[ni][1] = round_tf32(p1);
            sacc[ni][2] = round_tf32(p2);
            sacc[ni][3] = round_tf32(p3);
        }
        sum_lo += __shfl_xor_sync(0xffffffffu, sum_lo, 1);
        sum_lo += __shfl_xor_sync(0xffffffffu, sum_lo, 2);
        sum_hi += __shfl_xor_sync(0xffffffffu, sum_hi, 1);
        sum_hi += __shfl_xor_sync(0xffffffffu, sum_hi, 2);
        l_lo = l_lo * al_lo + sum_lo;
        l_hi = l_hi * al_hi + sum_hi;

        // ---- rescale O ----
        #pragma unroll
        for (int nt = 0; nt < 16; nt++) {
            O[nt][0] *= al_lo;  O[nt][1] *= al_lo;
            O[nt][2] *= al_hi;  O[nt][3] *= al_hi;
        }

        // ---- O += P @ V  (P re-fragmented via quad shuffles) ----
        const int src0 = (lane & ~3) | (t4 >> 1);
        const int src1 = src0 + 2;
        const bool odd = (t4 & 1);
        #pragma unroll
        for (int kb = 0; kb < 4; kb++) {
            float v00 = __shfl_sync(0xffffffffu, sacc[kb][0], src0);
            float v01 = __shfl_sync(0xffffffffu, sacc[kb][1], src0);
            float v10 = __shfl_sync(0xffffffffu, sacc[kb][2], src0);
            float v11 = __shfl_sync(0xffffffffu, sacc[kb][3], src0);
            float v20 = __shfl_sync(0xffffffffu, sacc[kb][0], src1);
            float v21 = __shfl_sync(0xffffffffu, sacc[kb][1], src1);
            float v30 = __shfl_sync(0xffffffffu, sacc[kb][2], src1);
            float v31 = __shfl_sync(0xffffffffu, sacc[kb][3], src1);
            uint32_t af[4];
            af[0] = __float_as_uint(odd ? v01 : v00);
            af[1] = __float_as_uint(odd ? v11 : v10);
            af[2] = __float_as_uint(odd ? v21 : v20);
            af[3] = __float_as_uint(odd ? v31 : v30);
            #pragma unroll
            for (int nt = 0; nt < 16; nt++) {
                uint32_t bf[2];
                const float* vp = Vs + (kb * 8 + t4) * VSTR + nt * 8 + g;
                bf[0] = __float_as_uint(vp[0]);
                bf[1] = __float_as_uint(vp[4 * VSTR]);
                mma_tf32(O[nt], af, bf);
            }
        }

        __syncthreads();                       // all warps done with Ks/Vs
        if (kt + 1 < nIter) {
            loadKV((kt + 1) * AT_BK);
            cp_commit();
            cp_wait0();
        }
        __syncthreads();                       // next tile visible
    }

    // ---- finalize: /l, round to tf32, write [B][S][H] ----
    const int h = bh & (NH_ - 1);
    const float inv_lo = 1.f / l_lo;
    const float inv_hi = 1.f / l_hi;
    const int q_lo = q0 + rowA;
    float* dst_lo = out + ((size_t)b * S_ + q_lo) * H_ + h * HD_;
    float* dst_hi = dst_lo + (size_t)8 * H_;
    #pragma unroll
    for (int nt = 0; nt < 16; nt++) {
        const int col = nt * 8 + 2 * t4;
        *(float2*)&dst_lo[col] = make_float2(round_tf32(O[nt][0] * inv_lo),
                                             round_tf32(O[nt][1] * inv_lo));
        *(float2*)&dst_hi[col] = make_float2(round_tf32(O[nt][2] * inv_hi),
                                             round_tf32(O[nt][3] * inv_hi));
    }
}

// ---------------------------------------------------------------------------
// Launch
// ---------------------------------------------------------------------------
extern "C" void kernel_launch(void* const* d_in, const int* in_sizes, int n_in,
                              void* d_out, int out_size)
{
    const float* x    = (const float*)d_in[0];
    const float* mask = (const float*)d_in[1];
    const float* Wq   = (const float*)d_in[2];
    const float* bq   = (const float*)d_in[3];
    const float* Wk   = (const float*)d_in[4];
    const float* bk   = (const float*)d_in[5];
    const float* Wv   = (const float*)d_in[6];
    const float* bv   = (const float*)d_in[7];
    const float* Wo   = (const float*)d_in[8];
    const float* bo   = (const float*)d_in[9];
    float* out = (float*)d_out;

    float *q, *k, *v, *attn, *xt, *wt;
    cudaGetSymbolAddress((void**)&q,    g_q);
    cudaGetSymbolAddress((void**)&k,    g_k);
    cudaGetSymbolAddress((void**)&v,    g_v);
    cudaGetSymbolAddress((void**)&attn, g_attn);
    cudaGetSymbolAddress((void**)&xt,   g_xt);
    cudaGetSymbolAddress((void**)&wt,   g_wt);

    cudaFuncSetAttribute(gemm_tf32<true>,
                         cudaFuncAttributeMaxDynamicSharedMemorySize, G_SMEM);
    cudaFuncSetAttribute(gemm_tf32<false>,
                         cudaFuncAttributeMaxDynamicSharedMemorySize, G_SMEM);
    cudaFuncSetAttribute(attn_tf32,
                         cudaFuncAttributeMaxDynamicSharedMemorySize, AT_SMEM);

    // Pre-round inputs/weights to tf32
    const int nx4 = MTOT * H_ / 4;
    const int nw4 = H_ * H_ / 4;
    const size_t wsz = (size_t)H_ * H_;
    roundcast<<<(nx4 + 255) / 256, 256>>>(x,  xt,           nx4);
    roundcast<<<(nw4 + 255) / 256, 256>>>(Wq, wt + 0 * wsz, nw4);
    roundcast<<<(nw4 + 255) / 256, 256>>>(Wk, wt + 1 * wsz, nw4);
    roundcast<<<(nw4 + 255) / 256, 256>>>(Wv, wt + 2 * wsz, nw4);
    roundcast<<<(nw4 + 255) / 256, 256>>>(Wo, wt + 3 * wsz, nw4);

    dim3 ggrid(H_ / 128, MTOT / 128);   // (16, 32)

    gemm_tf32<true><<<ggrid, 256, G_SMEM>>>(xt, wt + 0 * wsz, bq, q, MTOT, H_, H_);
    gemm_tf32<true><<<ggrid, 256, G_SMEM>>>(xt, wt + 1 * wsz, bk, k, MTOT, H_, H_);
    gemm_tf32<true><<<ggrid, 256, G_SMEM>>>(xt, wt + 2 * wsz, bv, v, MTOT, H_, H_);

    attn_tf32<<<dim3(S_ / AT_BQ, B_ * NH_), 256, AT_SMEM>>>(q, k, v, mask, attn);

    gemm_tf32<false><<<ggrid, 256, G_SMEM>>>(attn, wt + 3 * wsz, bo, out, MTOT, H_, H_);
}

// round 6
// speedup vs baseline: 5.4472x; 1.0138x over previous
#include <cuda_runtime.h>
#include <math.h>
#include <stdint.h>

// Problem constants
#define B_   2
#define S_   2048
#define H_   2048
#define NH_  16
#define HD_  128
#define MTOT (B_ * S_)          // 4096 rows for projection GEMMs

// ---------------------------------------------------------------------------
// Device scratch
// ---------------------------------------------------------------------------
__device__ float g_q[(size_t)B_ * NH_ * S_ * HD_];
__device__ float g_k[(size_t)B_ * NH_ * S_ * HD_];
__device__ float g_v[(size_t)B_ * NH_ * S_ * HD_];
__device__ float g_attn[(size_t)B_ * S_ * H_];
__device__ float g_xt[(size_t)MTOT * H_];          // tf32-rounded x
__device__ float g_wt[(size_t)4 * H_ * H_];        // W^T (K-major), tf32-rounded

// ---------------------------------------------------------------------------
// Helpers
// ---------------------------------------------------------------------------
__device__ __forceinline__ uint32_t cvt_tf32(float f) {
    uint32_t u;
    asm("cvt.rna.tf32.f32 %0, %1;" : "=r"(u) : "f"(f));
    return u;
}
__device__ __forceinline__ float round_tf32(float f) {
    return __uint_as_float(cvt_tf32(f));
}
__device__ __forceinline__ void cp16(void* s, const void* g) {
    uint32_t sa = (uint32_t)__cvta_generic_to_shared(s);
    asm volatile("cp.async.cg.shared.global [%0], [%1], 16;" :: "r"(sa), "l"(g));
}
__device__ __forceinline__ void cp_commit() {
    asm volatile("cp.async.commit_group;");
}
template <int N>
__device__ __forceinline__ void cp_wait() {
    asm volatile("cp.async.wait_group %0;" :: "n"(N));
}
__device__ __forceinline__ void cp_wait0() {
    asm volatile("cp.async.wait_group 0;");
}

// m16n8k8 TF32 mma. Fragment layouts (g=lane>>2, t4=lane&3):
//   A: a0=(g,t4) a1=(g+8,t4) a2=(g,t4+4) a3=(g+8,t4+4)   [row, k]
//   B: b0=(k=t4, n=g) b1=(k=t4+4, n=g)
//   C: c0=(g,2t4) c1=(g,2t4+1) c2=(g+8,2t4) c3=(g+8,2t4+1)
__device__ __forceinline__ void mma_tf32(float (&c)[4], const uint32_t (&a)[4],
                                         const uint32_t (&b)[2]) {
    asm volatile(
        "mma.sync.aligned.m16n8k8.row.col.f32.tf32.tf32.f32 "
        "{%0,%1,%2,%3}, {%4,%5,%6,%7}, {%8,%9}, {%0,%1,%2,%3};\n"
        : "+f"(c[0]), "+f"(c[1]), "+f"(c[2]), "+f"(c[3])
        : "r"(a[0]), "r"(a[1]), "r"(a[2]), "r"(a[3]), "r"(b[0]), "r"(b[1]));
}

// ---------------------------------------------------------------------------
// Prep kernels
// ---------------------------------------------------------------------------
__global__ void roundcast(const float* __restrict__ src, float* __restrict__ dst,
                          int n4)
{
    int i = blockIdx.x * blockDim.x + threadIdx.x;
    if (i < n4) {
        float4 v = ((const float4*)src)[i];
        v.x = round_tf32(v.x);
        v.y = round_tf32(v.y);
        v.z = round_tf32(v.z);
        v.w = round_tf32(v.w);
        ((float4*)dst)[i] = v;
    }
}

// Wt[n][k] = round_tf32(W[k][n])  (K-major weight rows)
__global__ void transpose_round(const float* __restrict__ W, float* __restrict__ Wt)
{
    __shared__ float t[32][33];
    int n0 = blockIdx.x * 32, k0 = blockIdx.y * 32;
    int tx = threadIdx.x, ty = threadIdx.y;
    #pragma unroll
    for (int i = 0; i < 4; i++)
        t[ty + i * 8][tx] = W[(size_t)(k0 + ty + i * 8) * H_ + n0 + tx];
    __syncthreads();
    #pragma unroll
    for (int i = 0; i < 4; i++)
        Wt[(size_t)(n0 + ty + i * 8) * H_ + k0 + tx] = round_tf32(t[tx][ty + i * 8]);
}

// ---------------------------------------------------------------------------
// TF32 GEMM, 3-stage cp.async pipeline (prefetch distance 2).
// A [M][K] row-major, Wt [N][K] K-major — both tiles 128x32, stride 36.
// 8 warps (2x4), warp tile 64x32. One __syncthreads per K-iter.
// FUSED=true: N spans 3 stacked weight matrices (Q,K,V); epilogue rounds and
// scatters to [B][NH][S][HD] of out0/1/2. FUSED=false: plain C = A@W + bias.
// ---------------------------------------------------------------------------
#define GP_STR  36
#define GP_STGF (2 * 128 * GP_STR)                 // floats per stage (9216)
#define GP_SMEM (3 * GP_STGF * 4)                  // 110592 B

template <bool FUSED>
__global__ __launch_bounds__(256, 2)
void gemm_pipe(const float* __restrict__ A, const float* __restrict__ Wt,
               const float* __restrict__ b0, const float* __restrict__ b1,
               const float* __restrict__ b2,
               float* __restrict__ o0, float* __restrict__ o1,
               float* __restrict__ o2)
{
    constexpr int BK = 32;
    constexpr int K = H_;
    extern __shared__ float sm[];

    const int tid = threadIdx.x;
    const int w = tid >> 5, lane = tid & 31, g = lane >> 2, t4 = lane & 3;
    const int wr = w >> 2, wc = w & 3;          // warp grid 2x4
    const int mBase = blockIdx.y * 128;
    const int nBase = blockIdx.x * 128;

    float acc[4][4][4] = {};

    // stage loader: A rows 0..127 then W rows 0..127, 8 cp16 per thread
    auto loadStage = [&](int kt, int s) {
        float* St = sm + s * GP_STGF;
        const int k0 = kt * BK;
        #pragma unroll
        for (int i = 0; i < 4; i++) {
            int id = tid + i * 256;
            int r = id >> 3, c4 = (id & 7) * 4;
            cp16(St + r * GP_STR + c4, A + (size_t)(mBase + r) * K + k0 + c4);
        }
        #pragma unroll
        for (int i = 0; i < 4; i++) {
            int id = tid + i * 256;
            int r = id >> 3, c4 = (id & 7) * 4;
            cp16(St + (128 + r) * GP_STR + c4,
                 Wt + (size_t)(nBase + r) * K + k0 + c4);
        }
    };

    const int nIter = K / BK;   // 64
    loadStage(0, 0); cp_commit();
    loadStage(1, 1); cp_commit();

    for (int kt = 0; kt < nIter; kt++) {
        cp_wait<1>();           // tile kt's group complete (kt+1 may pend)
        __syncthreads();        // visibility + all warps done with buf (kt+2)%3

        const int nt = kt + 2;
        if (nt < nIter) loadStage(nt, nt % 3);
        cp_commit();            // always commit (group accounting)

        const float* Ab = sm + (kt % 3) * GP_STGF;
        const float* Bb = Ab + 128 * GP_STR;

        #pragma unroll
        for (int k8 = 0; k8 < 4; k8++) {
            uint32_t af[4][4], bf[4][2];
            #pragma unroll
            for (int mi = 0; mi < 4; mi++) {
                const float* p = Ab + (wr * 64 + mi * 16 + g) * GP_STR + k8 * 8 + t4;
                af[mi][0] = __float_as_uint(p[0]);
                af[mi][1] = __float_as_uint(p[8 * GP_STR]);
                af[mi][2] = __float_as_uint(p[4]);
                af[mi][3] = __float_as_uint(p[8 * GP_STR + 4]);
            }
            #pragma unroll
            for (int ni = 0; ni < 4; ni++) {
                const float* p = Bb + (wc * 32 + ni * 8 + g) * GP_STR + k8 * 8 + t4;
                bf[ni][0] = __float_as_uint(p[0]);
                bf[ni][1] = __float_as_uint(p[4]);
            }
            #pragma unroll
            for (int mi = 0; mi < 4; mi++)
                #pragma unroll
                for (int ni = 0; ni < 4; ni++)
                    mma_tf32(acc[mi][ni], af[mi], bf[ni]);
        }
    }

    // Epilogue
    #pragma unroll
    for (int mi = 0; mi < 4; mi++) {
        #pragma unroll
        for (int r2 = 0; r2 < 2; r2++) {
            const int m = mBase + wr * 64 + mi * 16 + g + r2 * 8;
            #pragma unroll
            for (int ni = 0; ni < 4; ni++) {
                const int n = nBase + wc * 32 + ni * 8 + 2 * t4;
                if (FUSED) {
                    const int which = n >> 11;        // 0=Q 1=K 2=V
                    const int n2 = n & (H_ - 1);
                    const float* bias = (which == 0) ? b0 : (which == 1) ? b1 : b2;
                    float* dst = (which == 0) ? o0 : (which == 1) ? o1 : o2;
                    float2 v;
                    v.x = round_tf32(acc[mi][ni][r2 * 2 + 0] + bias[n2]);
                    v.y = round_tf32(acc[mi][ni][r2 * 2 + 1] + bias[n2 + 1]);
                    const int b = m >> 11;
                    const int s = m & (S_ - 1);
                    const int h = n2 >> 7;
                    const int d = n2 & (HD_ - 1);
                    *(float2*)&dst[(((size_t)(b * NH_ + h)) * S_ + s) * HD_ + d] = v;
                } else {
                    float2 v;
                    v.x = acc[mi][ni][r2 * 2 + 0] + b0[n];
                    v.y = acc[mi][ni][r2 * 2 + 1] + b0[n + 1];
                    *(float2*)&o0[(size_t)m * H_ + n] = v;
                }
            }
        }
    }
}

// ---------------------------------------------------------------------------
// TF32 flash attention v2 (unchanged from Round 5 — known passing).
// ---------------------------------------------------------------------------
#define AT_BQ  128
#define AT_BK  32
#define QSTR   132
#define KSTR   132
#define VSTR   136
#define AT_SMEM ((AT_BQ*QSTR + AT_BK*KSTR + AT_BK*VSTR + AT_BK) * 4)  // 102016 B

__global__ __launch_bounds__(256, 2)
void attn_tf32(const float* __restrict__ Q, const float* __restrict__ K,
               const float* __restrict__ V, const float* __restrict__ mask,
               float* __restrict__ out)
{
    extern __shared__ float sm[];
    float* Qs  = sm;                       // 128 x 132
    float* Ks  = Qs + AT_BQ * QSTR;        // 32 x 132
    float* Vs  = Ks + AT_BK * KSTR;        // 32 x 136
    float* msk = Vs + AT_BK * VSTR;        // 32

    const int tid = threadIdx.x;
    const int w = tid >> 5, lane = tid & 31, g = lane >> 2, t4 = lane & 3;
    const int bh = blockIdx.y;
    const int b  = bh >> 4;                // bh / NH_
    const int q0 = blockIdx.x * AT_BQ;

    const float* Qg = Q + ((size_t)bh * S_ + q0) * HD_;
    const float* Kg = K + (size_t)bh * S_ * HD_;
    const float* Vg = V + (size_t)bh * S_ * HD_;
    const float* maskg = mask + (size_t)b * S_;

    #pragma unroll
    for (int i = 0; i < 16; i++) {
        int id = tid + i * 256;
        int r = id >> 5, c4 = (id & 31) * 4;
        cp16(Qs + r * QSTR + c4, Qg + (size_t)r * HD_ + c4);
    }
    auto loadKV = [&](int kb0) {
        #pragma unroll
        for (int i = 0; i < 4; i++) {
            int id = tid + i * 256;
            int r = id >> 5, c4 = (id & 31) * 4;
            cp16(Ks + r * KSTR + c4, Kg + (size_t)(kb0 + r) * HD_ + c4);
            cp16(Vs + r * VSTR + c4, Vg + (size_t)(kb0 + r) * HD_ + c4);
        }
        if (tid < AT_BK) msk[tid] = maskg[kb0 + tid];
    };
    loadKV(0);
    cp_commit();
    cp_wait0();
    __syncthreads();

    float O[16][4];
    #pragma unroll
    for (int nt = 0; nt < 16; nt++)
        #pragma unroll
        for (int c = 0; c < 4; c++) O[nt][c] = 0.f;
    float m_lo = -1e30f, m_hi = -1e30f, l_lo = 0.f, l_hi = 0.f;

    const float scale = 0.08838834764831845f;   // 1/sqrt(128)
    const int nIter = S_ / AT_BK;               // 64
    const int rowA = w * 16 + g;

    for (int kt = 0; kt < nIter; kt++) {
        float sacc[4][4] = {};
        #pragma unroll
        for (int k8 = 0; k8 < 16; k8++) {
            uint32_t af[4];
            const float* qp = Qs + rowA * QSTR + k8 * 8 + t4;
            af[0] = __float_as_uint(qp[0]);
            af[1] = __float_as_uint(qp[8 * QSTR]);
            af[2] = __float_as_uint(qp[4]);
            af[3] = __float_as_uint(qp[8 * QSTR + 4]);
            #pragma unroll
            for (int ni = 0; ni < 4; ni++) {
                uint32_t bf[2];
                const float* kp = Ks + (ni * 8 + g) * KSTR + k8 * 8 + t4;
                bf[0] = __float_as_uint(kp[0]);
                bf[1] = __float_as_uint(kp[4]);
                mma_tf32(sacc[ni], af, bf);
            }
        }

        #pragma unroll
        for (int ni = 0; ni < 4; ni++)
            #pragma unroll
            for (int c = 0; c < 4; c++) {
                const int col = ni * 8 + 2 * t4 + (c & 1);
                sacc[ni][c] = sacc[ni][c] * scale + msk[col];
            }

        float rm_lo = -1e30f, rm_hi = -1e30f;
        #pragma unroll
        for (int ni = 0; ni < 4; ni++) {
            rm_lo = fmaxf(rm_lo, fmaxf(sacc[ni][0], sacc[ni][1]));
            rm_hi = fmaxf(rm_hi, fmaxf(sacc[ni][2], sacc[ni][3]));
        }
        rm_lo = fmaxf(rm_lo, __shfl_xor_sync(0xffffffffu, rm_lo, 1));
        rm_lo = fmaxf(rm_lo, __shfl_xor_sync(0xffffffffu, rm_lo, 2));
        rm_hi = fmaxf(rm_hi, __shfl_xor_sync(0xffffffffu, rm_hi, 1));
        rm_hi = fmaxf(rm_hi, __shfl_xor_sync(0xffffffffu, rm_hi, 2));

        const float mn_lo = fmaxf(m_lo, rm_lo);
        const float mn_hi = fmaxf(m_hi, rm_hi);
        const float al_lo = __expf(m_lo - mn_lo);
        const float al_hi = __expf(m_hi - mn_hi);
        m_lo = mn_lo;
        m_hi = mn_hi;

        float sum_lo = 0.f, sum_hi = 0.f;
        #pragma unroll
        for (int ni = 0; ni < 4; ni++) {
            float p0 = __expf(sacc[ni][0] - mn_lo);
            float p1 = __expf(sacc[ni][1] - mn_lo);
            float p2 = __expf(sacc[ni][2] - mn_hi);
            float p3 = __expf(sacc[ni][3] - mn_hi);
            sum_lo += p0 + p1;
            sum_hi += p2 + p3;
            sacc[ni][0] = round_tf32(p0);
            sacc[ni][1] = round_tf32(p1);
            sacc[ni][2] = round_tf32(p2);
            sacc[ni][3] = round_tf32(p3);
        }
        sum_lo += __shfl_xor_sync(0xffffffffu, sum_lo, 1);
        sum_lo += __shfl_xor_sync(0xffffffffu, sum_lo, 2);
        sum_hi += __shfl_xor_sync(0xffffffffu, sum_hi, 1);
        sum_hi += __shfl_xor_sync(0xffffffffu, sum_hi, 2);
        l_lo = l_lo * al_lo + sum_lo;
        l_hi = l_hi * al_hi + sum_hi;

        #pragma unroll
        for (int nt = 0; nt < 16; nt++) {
            O[nt][0] *= al_lo;  O[nt][1] *= al_lo;
            O[nt][2] *= al_hi;  O[nt][3] *= al_hi;
        }

        const int src0 = (lane & ~3) | (t4 >> 1);
        const int src1 = src0 + 2;
        const bool odd = (t4 & 1);
        #pragma unroll
        for (int kb = 0; kb < 4; kb++) {
            float v00 = __shfl_sync(0xffffffffu, sacc[kb][0], src0);
            float v01 = __shfl_sync(0xffffffffu, sacc[kb][1], src0);
            float v10 = __shfl_sync(0xffffffffu, sacc[kb][2], src0);
            float v11 = __shfl_sync(0xffffffffu, sacc[kb][3], src0);
            float v20 = __shfl_sync(0xffffffffu, sacc[kb][0], src1);
            float v21 = __shfl_sync(0xffffffffu, sacc[kb][1], src1);
            float v30 = __shfl_sync(0xffffffffu, sacc[kb][2], src1);
            float v31 = __shfl_sync(0xffffffffu, sacc[kb][3], src1);
            uint32_t af[4];
            af[0] = __float_as_uint(odd ? v01 : v00);
            af[1] = __float_as_uint(odd ? v11 : v10);
            af[2] = __float_as_uint(odd ? v21 : v20);
            af[3] = __float_as_uint(odd ? v31 : v30);
            #pragma unroll
            for (int nt = 0; nt < 16; nt++) {
                uint32_t bf[2];
                const float* vp = Vs + (kb * 8 + t4) * VSTR + nt * 8 + g;
                bf[0] = __float_as_uint(vp[0]);
                bf[1] = __float_as_uint(vp[4 * VSTR]);
                mma_tf32(O[nt], af, bf);
            }
        }

        __syncthreads();
        if (kt + 1 < nIter) {
            loadKV((kt + 1) * AT_BK);
            cp_commit();
            cp_wait0();
        }
        __syncthreads();
    }

    const int h = bh & (NH_ - 1);
    const float inv_lo = 1.f / l_lo;
    const float inv_hi = 1.f / l_hi;
    const int q_lo = q0 + rowA;
    float* dst_lo = out + ((size_t)b * S_ + q_lo) * H_ + h * HD_;
    float* dst_hi = dst_lo + (size_t)8 * H_;
    #pragma unroll
    for (int nt = 0; nt < 16; nt++) {
        const int col = nt * 8 + 2 * t4;
        *(float2*)&dst_lo[col] = make_float2(round_tf32(O[nt][0] * inv_lo),
                                             round_tf32(O[nt][1] * inv_lo));
        *(float2*)&dst_hi[col] = make_float2(round_tf32(O[nt][2] * inv_hi),
                                             round_tf32(O[nt][3] * inv_hi));
    }
}

// ---------------------------------------------------------------------------
// Launch
// ---------------------------------------------------------------------------
extern "C" void kernel_launch(void* const* d_in, const int* in_sizes, int n_in,
                              void* d_out, int out_size)
{
    const float* x    = (const float*)d_in[0];
    const float* mask = (const float*)d_in[1];
    const float* Wq   = (const float*)d_in[2];
    const float* bq   = (const float*)d_in[3];
    const float* Wk   = (const float*)d_in[4];
    const float* bk   = (const float*)d_in[5];
    const float* Wv   = (const float*)d_in[6];
    const float* bv   = (const float*)d_in[7];
    const float* Wo   = (const float*)d_in[8];
    const float* bo   = (const float*)d_in[9];
    float* out = (float*)d_out;

    float *q, *k, *v, *attn, *xt, *wt;
    cudaGetSymbolAddress((void**)&q,    g_q);
    cudaGetSymbolAddress((void**)&k,    g_k);
    cudaGetSymbolAddress((void**)&v,    g_v);
    cudaGetSymbolAddress((void**)&attn, g_attn);
    cudaGetSymbolAddress((void**)&xt,   g_xt);
    cudaGetSymbolAddress((void**)&wt,   g_wt);

    cudaFuncSetAttribute(gemm_pipe<true>,
                         cudaFuncAttributeMaxDynamicSharedMemorySize, GP_SMEM);
    cudaFuncSetAttribute(gemm_pipe<false>,
                         cudaFuncAttributeMaxDynamicSharedMemorySize, GP_SMEM);
    cudaFuncSetAttribute(attn_tf32,
                         cudaFuncAttributeMaxDynamicSharedMemorySize, AT_SMEM);

    // Prep: round x; transpose+round weights to K-major [N][K], stacked QKV+O
    const int nx4 = MTOT * H_ / 4;
    const size_t wsz = (size_t)H_ * H_;
    roundcast<<<(nx4 + 255) / 256, 256>>>(x, xt, nx4);
    dim3 tgrid(H_ / 32, H_ / 32), tblk(32, 8);
    transpose_round<<<tgrid, tblk>>>(Wq, wt + 0 * wsz);
    transpose_round<<<tgrid, tblk>>>(Wk, wt + 1 * wsz);
    transpose_round<<<tgrid, tblk>>>(Wv, wt + 2 * wsz);
    transpose_round<<<tgrid, tblk>>>(Wo, wt + 3 * wsz);

    // Fused QKV projection: N = 3*2048 over stacked weights
    gemm_pipe<true><<<dim3(3 * H_ / 128, MTOT / 128), 256, GP_SMEM>>>(
        xt, wt, bq, bk, bv, q, k, v);

    attn_tf32<<<dim3(S_ / AT_BQ, B_ * NH_), 256, AT_SMEM>>>(q, k, v, mask, attn);

    // Out projection
    gemm_pipe<false><<<dim3(H_ / 128, MTOT / 128), 256, GP_SMEM>>>(
        attn, wt + 3 * wsz, bo, nullptr, nullptr, out, nullptr, nullptr);
}

// round 7
// speedup vs baseline: 10.6302x; 1.9515x over previous
#include <cuda_runtime.h>
#include <cuda_fp16.h>
#include <math.h>
#include <stdint.h>

// Problem constants
#define B_   2
#define S_   2048
#define H_   2048
#define NH_  16
#define HD_  128
#define MTOT (B_ * S_)          // 4096 rows for projection GEMMs

// ---------------------------------------------------------------------------
// Device scratch (half precision operands everywhere)
// ---------------------------------------------------------------------------
__device__ __half g_q[(size_t)B_ * NH_ * S_ * HD_];
__device__ __half g_k[(size_t)B_ * NH_ * S_ * HD_];
__device__ __half g_v[(size_t)B_ * NH_ * S_ * HD_];
__device__ __half g_attn[(size_t)B_ * S_ * H_];
__device__ __half g_xh[(size_t)MTOT * H_];         // fp16 x
__device__ __half g_wt[(size_t)4 * H_ * H_];       // W^T (K-major), fp16

// ---------------------------------------------------------------------------
// Helpers
// ---------------------------------------------------------------------------
__device__ __forceinline__ uint32_t smem_u32(const void* p) {
    return (uint32_t)__cvta_generic_to_shared(p);
}
__device__ __forceinline__ void cp16(void* s, const void* g) {
    asm volatile("cp.async.cg.shared.global [%0], [%1], 16;"
                 :: "r"(smem_u32(s)), "l"(g));
}
__device__ __forceinline__ void cp_commit() {
    asm volatile("cp.async.commit_group;");
}
template <int N>
__device__ __forceinline__ void cp_wait() {
    asm volatile("cp.async.wait_group %0;" :: "n"(N));
}

__device__ __forceinline__ void ldmx4(uint32_t (&r)[4], uint32_t a) {
    asm volatile("ldmatrix.sync.aligned.m8n8.x4.shared.b16 {%0,%1,%2,%3}, [%4];"
                 : "=r"(r[0]), "=r"(r[1]), "=r"(r[2]), "=r"(r[3]) : "r"(a));
}
__device__ __forceinline__ void ldmx4t(uint32_t (&r)[4], uint32_t a) {
    asm volatile("ldmatrix.sync.aligned.m8n8.x4.trans.shared.b16 {%0,%1,%2,%3}, [%4];"
                 : "=r"(r[0]), "=r"(r[1]), "=r"(r[2]), "=r"(r[3]) : "r"(a));
}

// m16n8k16 fp16 mma, fp32 accumulate.
// A frag (4 .f16x2): a0=(g, 2t4|+1) a1=(g+8, ..) a2=(g, 8+2t4|+1) a3=(g+8, ..)
// B frag (2 .f16x2): b0=(k=2t4|+1, n=g) b1=(k=8+2t4|+1, n=g)
// C frag (4 .f32):   c0=(g,2t4) c1=(g,2t4+1) c2=(g+8,2t4) c3=(g+8,2t4+1)
__device__ __forceinline__ void mma_f16(float (&c)[4], const uint32_t (&a)[4],
                                        uint32_t b0, uint32_t b1) {
    asm volatile(
        "mma.sync.aligned.m16n8k16.row.col.f32.f16.f16.f32 "
        "{%0,%1,%2,%3}, {%4,%5,%6,%7}, {%8,%9}, {%0,%1,%2,%3};\n"
        : "+f"(c[0]), "+f"(c[1]), "+f"(c[2]), "+f"(c[3])
        : "r"(a[0]), "r"(a[1]), "r"(a[2]), "r"(a[3]), "r"(b0), "r"(b1));
}

__device__ __forceinline__ uint32_t packh2(float lo, float hi) {
    __half2 h = __float22half2_rn(make_float2(lo, hi));
    return *reinterpret_cast<uint32_t*>(&h);
}

// ---------------------------------------------------------------------------
// Prep: x -> fp16; W -> W^T fp16 (K-major rows)
// ---------------------------------------------------------------------------
__global__ void halfcast(const float* __restrict__ src, __half* __restrict__ dst,
                         int n4)
{
    int i = blockIdx.x * blockDim.x + threadIdx.x;
    if (i < n4) {
        float4 v = ((const float4*)src)[i];
        uint2 o;
        o.x = packh2(v.x, v.y);
        o.y = packh2(v.z, v.w);
        ((uint2*)dst)[i] = o;
    }
}

__global__ void transpose_half(const float* __restrict__ W, __half* __restrict__ Wt)
{
    __shared__ float t[32][33];
    int n0 = blockIdx.x * 32, k0 = blockIdx.y * 32;
    int tx = threadIdx.x, ty = threadIdx.y;
    #pragma unroll
    for (int i = 0; i < 4; i++)
        t[ty + i * 8][tx] = W[(size_t)(k0 + ty + i * 8) * H_ + n0 + tx];
    __syncthreads();
    #pragma unroll
    for (int i = 0; i < 4; i++)
        Wt[(size_t)(n0 + ty + i * 8) * H_ + k0 + tx] = __float2half(t[tx][ty + i * 8]);
}

// ---------------------------------------------------------------------------
// fp16 GEMM, 3-stage cp.async pipeline: C = A(MxK) @ Wt^T + bias
// A [M][K] half, Wt [N][K] half. Tiles 128x32 halves, row stride 80 B
// (i*20 mod 32 -> conflict-free 8-row ldmatrix phases).
// 8 warps (2x4), warp tile 64x32. FUSED: N spans stacked Q,K,V weights,
// epilogue converts to half and scatters to [B][NH][S][HD].
// ---------------------------------------------------------------------------
#define GH_ROWB 80
#define GH_STGB (256 * GH_ROWB)            // 20480 B per stage (A 128 + B 128 rows)
#define GH_SMEM (3 * GH_STGB)              // 61440 B

template <bool FUSED>
__global__ __launch_bounds__(256, 2)
void gemm_h(const __half* __restrict__ A, const __half* __restrict__ Wt,
            const float* __restrict__ b0v, const float* __restrict__ b1v,
            const float* __restrict__ b2v,
            __half* __restrict__ o0, __half* __restrict__ o1,
            __half* __restrict__ o2, float* __restrict__ of)
{
    constexpr int BK = 32;                 // halves per K step
    constexpr int K = H_;
    extern __shared__ char smc[];
    const uint32_t sbase = smem_u32(smc);

    const int tid = threadIdx.x;
    const int w = tid >> 5, lane = tid & 31, g = lane >> 2, t4 = lane & 3;
    const int wr = w >> 2, wc = w & 3;
    const int mBase = blockIdx.y * 128;
    const int nBase = blockIdx.x * 128;

    float acc[4][4][4] = {};

    auto loadStage = [&](int kt, int s) {
        char* St = smc + s * GH_STGB;
        const int k0 = kt * BK;
        #pragma unroll
        for (int i = 0; i < 2; i++) {      // A: 512 chunks
            int id = tid + i * 256;
            int r = id >> 2, c = id & 3;
            cp16(St + r * GH_ROWB + c * 16,
                 A + (size_t)(mBase + r) * K + k0 + c * 8);
        }
        #pragma unroll
        for (int i = 0; i < 2; i++) {      // B: 512 chunks
            int id = tid + i * 256;
            int r = id >> 2, c = id & 3;
            cp16(St + (128 + r) * GH_ROWB + c * 16,
                 Wt + (size_t)(nBase + r) * K + k0 + c * 8);
        }
    };

    const int nIter = K / BK;   // 64
    loadStage(0, 0); cp_commit();
    loadStage(1, 1); cp_commit();

    // ldmatrix lane-address components
    const int aRow = wr * 64 + (lane & 15);
    const int aChunk = (lane >> 4) << 4;
    const int li = lane >> 3;
    const int bRowOff = ((li >> 1) << 3) + (lane & 7);
    const int bChunk = (li & 1) << 4;

    for (int kt = 0; kt < nIter; kt++) {
        cp_wait<1>();
        __syncthreads();

        const int nt = kt + 2;
        if (nt < nIter) loadStage(nt, nt % 3);
        cp_commit();

        const uint32_t Ab = sbase + (kt % 3) * GH_STGB;
        const uint32_t Bb = Ab + 128 * GH_ROWB;

        #pragma unroll
        for (int k16 = 0; k16 < 2; k16++) {
            uint32_t af[4][4], bf[2][4];
            #pragma unroll
            for (int mi = 0; mi < 4; mi++)
                ldmx4(af[mi], Ab + (aRow + mi * 16) * GH_ROWB + aChunk + k16 * 32);
            #pragma unroll
            for (int np = 0; np < 2; np++)
                ldmx4(bf[np], Bb + (wc * 32 + np * 16 + bRowOff) * GH_ROWB
                              + bChunk + k16 * 32);
            #pragma unroll
            for (int mi = 0; mi < 4; mi++)
                #pragma unroll
                for (int np = 0; np < 2; np++) {
                    mma_f16(acc[mi][np * 2 + 0], af[mi], bf[np][0], bf[np][1]);
                    mma_f16(acc[mi][np * 2 + 1], af[mi], bf[np][2], bf[np][3]);
                }
        }
    }

    // Epilogue
    #pragma unroll
    for (int mi = 0; mi < 4; mi++) {
        #pragma unroll
        for (int r2 = 0; r2 < 2; r2++) {
            const int m = mBase + wr * 64 + mi * 16 + g + r2 * 8;
            #pragma unroll
            for (int ni = 0; ni < 4; ni++) {
                const int n = nBase + wc * 32 + ni * 8 + 2 * t4;
                if (FUSED) {
                    const int which = n >> 11;        // 0=Q 1=K 2=V
                    const int n2 = n & (H_ - 1);
                    const float* bias = (which == 0) ? b0v : (which == 1) ? b1v : b2v;
                    __half* dst = (which == 0) ? o0 : (which == 1) ? o1 : o2;
                    const int b = m >> 11;
                    const int s = m & (S_ - 1);
                    const int h = n2 >> 7;
                    const int d = n2 & (HD_ - 1);
                    uint32_t pv = packh2(acc[mi][ni][r2 * 2 + 0] + bias[n2],
                                         acc[mi][ni][r2 * 2 + 1] + bias[n2 + 1]);
                    *(uint32_t*)&dst[(((size_t)(b * NH_ + h)) * S_ + s) * HD_ + d] = pv;
                } else {
                    float2 v;
                    v.x = acc[mi][ni][r2 * 2 + 0] + b0v[n];
                    v.y = acc[mi][ni][r2 * 2 + 1] + b0v[n + 1];
                    *(float2*)&of[(size_t)m * H_ + n] = v;
                }
            }
        }
    }
}

// ---------------------------------------------------------------------------
// fp16 flash attention. 8 warps x 16 rows, full N=32 / d=128 per warp.
// In-warp softmax; PV A-frags packed directly from S-accumulators (no
// shuffles); K via ldmatrix, V via ldmatrix.trans. Row stride 272 B
// (i*68 mod 32 conflict-free). Single-buffered K/V, 2 CTAs/SM.
// ---------------------------------------------------------------------------
#define AQ_ROWB 272
#define AT_SMEM (128 * AQ_ROWB + 32 * AQ_ROWB + 32 * AQ_ROWB + 128)   // 52352 B

__global__ __launch_bounds__(256, 2)
void attn_h(const __half* __restrict__ Q, const __half* __restrict__ K,
            const __half* __restrict__ V, const float* __restrict__ mask,
            __half* __restrict__ out)
{
    extern __shared__ char smc[];
    char* Qs = smc;                         // 128 x 272 B
    char* Ks = Qs + 128 * AQ_ROWB;          // 32 x 272 B
    char* Vs = Ks + 32 * AQ_ROWB;           // 32 x 272 B
    float* msk = (float*)(Vs + 32 * AQ_ROWB);   // 32 floats
    const uint32_t qbase = smem_u32(Qs);
    const uint32_t kbase = smem_u32(Ks);
    const uint32_t vbase = smem_u32(Vs);

    const int tid = threadIdx.x;
    const int w = tid >> 5, lane = tid & 31, g = lane >> 2, t4 = lane & 3;
    const int bh = blockIdx.y;
    const int b  = bh >> 4;
    const int q0 = blockIdx.x * 128;

    const __half* Qg = Q + ((size_t)bh * S_ + q0) * HD_;
    const __half* Kg = K + (size_t)bh * S_ * HD_;
    const __half* Vg = V + (size_t)bh * S_ * HD_;
    const float* maskg = mask + (size_t)b * S_;

    // Q tile: 128 rows x 256 B -> 2048 chunks
    #pragma unroll
    for (int i = 0; i < 8; i++) {
        int id = tid + i * 256;
        int r = id >> 4, c = id & 15;
        cp16(Qs + r * AQ_ROWB + c * 16, Qg + (size_t)r * HD_ + c * 8);
    }
    auto loadKV = [&](int kb0) {
        #pragma unroll
        for (int i = 0; i < 2; i++) {
            int id = tid + i * 256;
            int r = id >> 4, c = id & 15;
            cp16(Ks + r * AQ_ROWB + c * 16, Kg + (size_t)(kb0 + r) * HD_ + c * 8);
            cp16(Vs + r * AQ_ROWB + c * 16, Vg + (size_t)(kb0 + r) * HD_ + c * 8);
        }
        if (tid < 32) msk[tid] = maskg[kb0 + tid];
    };
    loadKV(0);
    cp_commit();
    cp_wait<0>();
    __syncthreads();

    float O[16][4];
    #pragma unroll
    for (int nt = 0; nt < 16; nt++)
        #pragma unroll
        for (int c = 0; c < 4; c++) O[nt][c] = 0.f;
    float m_lo = -1e30f, m_hi = -1e30f, l_lo = 0.f, l_hi = 0.f;

    const float scale = 0.08838834764831845f;   // 1/sqrt(128)
    const int nIter = S_ / 32;                  // 64

    // lane-address components
    const int aRow = (lane & 15);
    const int aChunk = (lane >> 4) << 4;
    const int li = lane >> 3;
    const int bRowOff = ((li >> 1) << 3) + (lane & 7);
    const int bChunk = (li & 1) << 4;
    const uint32_t qaddr0 = qbase + (w * 16 + aRow) * AQ_ROWB + aChunk;

    for (int kt = 0; kt < nIter; kt++) {
        // ---- S = Q @ K^T (16x32 per warp), K-dim = 128 = 8 k16 steps ----
        float sacc[4][4] = {};
        #pragma unroll
        for (int k16 = 0; k16 < 8; k16++) {
            uint32_t af[4], bf[2][4];
            ldmx4(af, qaddr0 + k16 * 32);
            #pragma unroll
            for (int np = 0; np < 2; np++)
                ldmx4(bf[np], kbase + (np * 16 + bRowOff) * AQ_ROWB
                              + bChunk + k16 * 32);
            #pragma unroll
            for (int np = 0; np < 2; np++) {
                mma_f16(sacc[np * 2 + 0], af, bf[np][0], bf[np][1]);
                mma_f16(sacc[np * 2 + 1], af, bf[np][2], bf[np][3]);
            }
        }

        // ---- scale + mask ----
        #pragma unroll
        for (int ni = 0; ni < 4; ni++)
            #pragma unroll
            for (int c = 0; c < 4; c++) {
                const int col = ni * 8 + 2 * t4 + (c & 1);
                sacc[ni][c] = sacc[ni][c] * scale + msk[col];
            }

        // ---- in-warp softmax ----
        float rm_lo = -1e30f, rm_hi = -1e30f;
        #pragma unroll
        for (int ni = 0; ni < 4; ni++) {
            rm_lo = fmaxf(rm_lo, fmaxf(sacc[ni][0], sacc[ni][1]));
            rm_hi = fmaxf(rm_hi, fmaxf(sacc[ni][2], sacc[ni][3]));
        }
        rm_lo = fmaxf(rm_lo, __shfl_xor_sync(0xffffffffu, rm_lo, 1));
        rm_lo = fmaxf(rm_lo, __shfl_xor_sync(0xffffffffu, rm_lo, 2));
        rm_hi = fmaxf(rm_hi, __shfl_xor_sync(0xffffffffu, rm_hi, 1));
        rm_hi = fmaxf(rm_hi, __shfl_xor_sync(0xffffffffu, rm_hi, 2));

        const float mn_lo = fmaxf(m_lo, rm_lo);
        const float mn_hi = fmaxf(m_hi, rm_hi);
        const float al_lo = __expf(m_lo - mn_lo);
        const float al_hi = __expf(m_hi - mn_hi);
        m_lo = mn_lo;
        m_hi = mn_hi;

        float sum_lo = 0.f, sum_hi = 0.f;
        #pragma unroll
        for (int ni = 0; ni < 4; ni++) {
            sacc[ni][0] = __expf(sacc[ni][0] - mn_lo);
            sacc[ni][1] = __expf(sacc[ni][1] - mn_lo);
            sacc[ni][2] = __expf(sacc[ni][2] - mn_hi);
            sacc[ni][3] = __expf(sacc[ni][3] - mn_hi);
            sum_lo += sacc[ni][0] + sacc[ni][1];
            sum_hi += sacc[ni][2] + sacc[ni][3];
        }
        sum_lo += __shfl_xor_sync(0xffffffffu, sum_lo, 1);
        sum_lo += __shfl_xor_sync(0xffffffffu, sum_lo, 2);
        sum_hi += __shfl_xor_sync(0xffffffffu, sum_hi, 1);
        sum_hi += __shfl_xor_sync(0xffffffffu, sum_hi, 2);
        l_lo = l_lo * al_lo + sum_lo;
        l_hi = l_hi * al_hi + sum_hi;

        #pragma unroll
        for (int nt = 0; nt < 16; nt++) {
            O[nt][0] *= al_lo;  O[nt][1] *= al_lo;
            O[nt][2] *= al_hi;  O[nt][3] *= al_hi;
        }

        // ---- O += P @ V : P packed straight from S accumulators ----
        #pragma unroll
        for (int kb = 0; kb < 2; kb++) {
            uint32_t af[4];
            af[0] = packh2(sacc[2 * kb][0],     sacc[2 * kb][1]);
            af[1] = packh2(sacc[2 * kb][2],     sacc[2 * kb][3]);
            af[2] = packh2(sacc[2 * kb + 1][0], sacc[2 * kb + 1][1]);
            af[3] = packh2(sacc[2 * kb + 1][2], sacc[2 * kb + 1][3]);
            #pragma unroll
            for (int t = 0; t < 8; t++) {
                uint32_t bf[4];
                ldmx4t(bf, vbase + (kb * 16 + aRow) * AQ_ROWB
                           + (2 * t) * 16 + aChunk);
                mma_f16(O[2 * t + 0], af, bf[0], bf[1]);
                mma_f16(O[2 * t + 1], af, bf[2], bf[3]);
            }
        }

        __syncthreads();
        if (kt + 1 < nIter) {
            loadKV((kt + 1) * 32);
            cp_commit();
            cp_wait<0>();
        }
        __syncthreads();
    }

    // ---- finalize: /l, convert to half, write [B][S][H] ----
    const int h = bh & (NH_ - 1);
    const float inv_lo = 1.f / l_lo;
    const float inv_hi = 1.f / l_hi;
    const int q_lo = q0 + w * 16 + g;
    __half* dst_lo = out + ((size_t)b * S_ + q_lo) * H_ + h * HD_;
    __half* dst_hi = dst_lo + (size_t)8 * H_;
    #pragma unroll
    for (int nt = 0; nt < 16; nt++) {
        const int col = nt * 8 + 2 * t4;
        *(uint32_t*)&dst_lo[col] = packh2(O[nt][0] * inv_lo, O[nt][1] * inv_lo);
        *(uint32_t*)&dst_hi[col] = packh2(O[nt][2] * inv_hi, O[nt][3] * inv_hi);
    }
}

// ---------------------------------------------------------------------------
// Launch
// ---------------------------------------------------------------------------
extern "C" void kernel_launch(void* const* d_in, const int* in_sizes, int n_in,
                              void* d_out, int out_size)
{
    const float* x    = (const float*)d_in[0];
    const float* mask = (const float*)d_in[1];
    const float* Wq   = (const float*)d_in[2];
    const float* bq   = (const float*)d_in[3];
    const float* Wk   = (const float*)d_in[4];
    const float* bk   = (const float*)d_in[5];
    const float* Wv   = (const float*)d_in[6];
    const float* bv   = (const float*)d_in[7];
    const float* Wo   = (const float*)d_in[8];
    const float* bo   = (const float*)d_in[9];
    float* out = (float*)d_out;

    __half *q, *k, *v, *attn, *xh, *wt;
    cudaGetSymbolAddress((void**)&q,    g_q);
    cudaGetSymbolAddress((void**)&k,    g_k);
    cudaGetSymbolAddress((void**)&v,    g_v);
    cudaGetSymbolAddress((void**)&attn, g_attn);
    cudaGetSymbolAddress((void**)&xh,   g_xh);
    cudaGetSymbolAddress((void**)&wt,   g_wt);

    cudaFuncSetAttribute(gemm_h<true>,
                         cudaFuncAttributeMaxDynamicSharedMemorySize, GH_SMEM);
    cudaFuncSetAttribute(gemm_h<false>,
                         cudaFuncAttributeMaxDynamicSharedMemorySize, GH_SMEM);
    cudaFuncSetAttribute(attn_h,
                         cudaFuncAttributeMaxDynamicSharedMemorySize, AT_SMEM);

    // Prep: x -> fp16; weights -> transposed fp16 (K-major), stacked Q,K,V,O
    const int nx4 = MTOT * H_ / 4;
    const size_t wsz = (size_t)H_ * H_;
    halfcast<<<(nx4 + 255) / 256, 256>>>(x, xh, nx4);
    dim3 tgrid(H_ / 32, H_ / 32), tblk(32, 8);
    transpose_half<<<tgrid, tblk>>>(Wq, wt + 0 * wsz);
    transpose_half<<<tgrid, tblk>>>(Wk, wt + 1 * wsz);
    transpose_half<<<tgrid, tblk>>>(Wv, wt + 2 * wsz);
    transpose_half<<<tgrid, tblk>>>(Wo, wt + 3 * wsz);

    // Fused QKV projection (N = 3*2048)
    gemm_h<true><<<dim3(3 * H_ / 128, MTOT / 128), 256, GH_SMEM>>>(
        xh, wt, bq, bk, bv, q, k, v, nullptr);

    attn_h<<<dim3(S_ / 128, B_ * NH_), 256, AT_SMEM>>>(q, k, v, mask, attn);

    // Out projection (fp32 output)
    gemm_h<false><<<dim3(H_ / 128, MTOT / 128), 256, GH_SMEM>>>(
        attn, wt + 3 * wsz, bo, nullptr, nullptr,
        nullptr, nullptr, nullptr, out);
}

// round 8
// speedup vs baseline: 11.2872x; 1.0618x over previous
#include <cuda_runtime.h>
#include <cuda_fp16.h>
#include <math.h>
#include <stdint.h>

// Problem constants
#define B_   2
#define S_   2048
#define H_   2048
#define NH_  16
#define HD_  128
#define MTOT (B_ * S_)          // 4096 rows for projection GEMMs

// ---------------------------------------------------------------------------
// Device scratch (half precision operands everywhere)
// ---------------------------------------------------------------------------
__device__ __half g_q[(size_t)B_ * NH_ * S_ * HD_];
__device__ __half g_k[(size_t)B_ * NH_ * S_ * HD_];
__device__ __half g_v[(size_t)B_ * NH_ * S_ * HD_];
__device__ __half g_attn[(size_t)B_ * S_ * H_];
__device__ __half g_xh[(size_t)MTOT * H_];         // fp16 x
__device__ __half g_wt[(size_t)4 * H_ * H_];       // W^T (K-major), fp16

// ---------------------------------------------------------------------------
// Helpers
// ---------------------------------------------------------------------------
__device__ __forceinline__ uint32_t smem_u32(const void* p) {
    return (uint32_t)__cvta_generic_to_shared(p);
}
__device__ __forceinline__ void cp16(void* s, const void* g) {
    asm volatile("cp.async.cg.shared.global [%0], [%1], 16;"
                 :: "r"(smem_u32(s)), "l"(g));
}
__device__ __forceinline__ void cp_commit() {
    asm volatile("cp.async.commit_group;");
}
template <int N>
__device__ __forceinline__ void cp_wait() {
    asm volatile("cp.async.wait_group %0;" :: "n"(N));
}

__device__ __forceinline__ void ldmx4(uint32_t (&r)[4], uint32_t a) {
    asm volatile("ldmatrix.sync.aligned.m8n8.x4.shared.b16 {%0,%1,%2,%3}, [%4];"
                 : "=r"(r[0]), "=r"(r[1]), "=r"(r[2]), "=r"(r[3]) : "r"(a));
}
__device__ __forceinline__ void ldmx4t(uint32_t (&r)[4], uint32_t a) {
    asm volatile("ldmatrix.sync.aligned.m8n8.x4.trans.shared.b16 {%0,%1,%2,%3}, [%4];"
                 : "=r"(r[0]), "=r"(r[1]), "=r"(r[2]), "=r"(r[3]) : "r"(a));
}

// m16n8k16 fp16 mma, fp32 accumulate.
__device__ __forceinline__ void mma_f16(float (&c)[4], const uint32_t (&a)[4],
                                        uint32_t b0, uint32_t b1) {
    asm volatile(
        "mma.sync.aligned.m16n8k16.row.col.f32.f16.f16.f32 "
        "{%0,%1,%2,%3}, {%4,%5,%6,%7}, {%8,%9}, {%0,%1,%2,%3};\n"
        : "+f"(c[0]), "+f"(c[1]), "+f"(c[2]), "+f"(c[3])
        : "r"(a[0]), "r"(a[1]), "r"(a[2]), "r"(a[3]), "r"(b0), "r"(b1));
}

__device__ __forceinline__ uint32_t packh2(float lo, float hi) {
    __half2 h = __float22half2_rn(make_float2(lo, hi));
    return *reinterpret_cast<uint32_t*>(&h);
}

// ---------------------------------------------------------------------------
// Prep: x -> fp16; all 4 weights -> W^T fp16 (K-major) in ONE launch (z picks)
// ---------------------------------------------------------------------------
__global__ void halfcast(const float* __restrict__ src, __half* __restrict__ dst,
                         int n4)
{
    int i = blockIdx.x * blockDim.x + threadIdx.x;
    if (i < n4) {
        float4 v = ((const float4*)src)[i];
        uint2 o;
        o.x = packh2(v.x, v.y);
        o.y = packh2(v.z, v.w);
        ((uint2*)dst)[i] = o;
    }
}

__global__ void transpose_half4(const float* __restrict__ W0,
                                const float* __restrict__ W1,
                                const float* __restrict__ W2,
                                const float* __restrict__ W3,
                                __half* __restrict__ Wt)
{
    const int z = blockIdx.z;
    const float* W = (z == 0) ? W0 : (z == 1) ? W1 : (z == 2) ? W2 : W3;
    __half* dst = Wt + (size_t)z * H_ * H_;

    __shared__ float t[32][33];
    int n0 = blockIdx.x * 32, k0 = blockIdx.y * 32;
    int tx = threadIdx.x, ty = threadIdx.y;
    #pragma unroll
    for (int i = 0; i < 4; i++)
        t[ty + i * 8][tx] = W[(size_t)(k0 + ty + i * 8) * H_ + n0 + tx];
    __syncthreads();
    #pragma unroll
    for (int i = 0; i < 4; i++)
        dst[(size_t)(n0 + ty + i * 8) * H_ + k0 + tx] = __float2half(t[tx][ty + i * 8]);
}

// ---------------------------------------------------------------------------
// fp16 GEMM, 3-stage cp.async pipeline (UNCHANGED from Round 7 — near pipe
// limit; protected). C = A(MxK) @ Wt^T + bias.
// ---------------------------------------------------------------------------
#define GH_ROWB 80
#define GH_STGB (256 * GH_ROWB)            // 20480 B per stage
#define GH_SMEM (3 * GH_STGB)              // 61440 B

template <bool FUSED>
__global__ __launch_bounds__(256, 2)
void gemm_h(const __half* __restrict__ A, const __half* __restrict__ Wt,
            const float* __restrict__ b0v, const float* __restrict__ b1v,
            const float* __restrict__ b2v,
            __half* __restrict__ o0, __half* __restrict__ o1,
            __half* __restrict__ o2, float* __restrict__ of)
{
    constexpr int BK = 32;
    constexpr int K = H_;
    extern __shared__ char smc[];
    const uint32_t sbase = smem_u32(smc);

    const int tid = threadIdx.x;
    const int w = tid >> 5, lane = tid & 31, g = lane >> 2, t4 = lane & 3;
    const int wr = w >> 2, wc = w & 3;
    const int mBase = blockIdx.y * 128;
    const int nBase = blockIdx.x * 128;

    float acc[4][4][4] = {};

    auto loadStage = [&](int kt, int s) {
        char* St = smc + s * GH_STGB;
        const int k0 = kt * BK;
        #pragma unroll
        for (int i = 0; i < 2; i++) {
            int id = tid + i * 256;
            int r = id >> 2, c = id & 3;
            cp16(St + r * GH_ROWB + c * 16,
                 A + (size_t)(mBase + r) * K + k0 + c * 8);
        }
        #pragma unroll
        for (int i = 0; i < 2; i++) {
            int id = tid + i * 256;
            int r = id >> 2, c = id & 3;
            cp16(St + (128 + r) * GH_ROWB + c * 16,
                 Wt + (size_t)(nBase + r) * K + k0 + c * 8);
        }
    };

    const int nIter = K / BK;   // 64
    loadStage(0, 0); cp_commit();
    loadStage(1, 1); cp_commit();

    const int aRow = wr * 64 + (lane & 15);
    const int aChunk = (lane >> 4) << 4;
    const int li = lane >> 3;
    const int bRowOff = ((li >> 1) << 3) + (lane & 7);
    const int bChunk = (li & 1) << 4;

    for (int kt = 0; kt < nIter; kt++) {
        cp_wait<1>();
        __syncthreads();

        const int nt = kt + 2;
        if (nt < nIter) loadStage(nt, nt % 3);
        cp_commit();

        const uint32_t Ab = sbase + (kt % 3) * GH_STGB;
        const uint32_t Bb = Ab + 128 * GH_ROWB;

        #pragma unroll
        for (int k16 = 0; k16 < 2; k16++) {
            uint32_t af[4][4], bf[2][4];
            #pragma unroll
            for (int mi = 0; mi < 4; mi++)
                ldmx4(af[mi], Ab + (aRow + mi * 16) * GH_ROWB + aChunk + k16 * 32);
            #pragma unroll
            for (int np = 0; np < 2; np++)
                ldmx4(bf[np], Bb + (wc * 32 + np * 16 + bRowOff) * GH_ROWB
                              + bChunk + k16 * 32);
            #pragma unroll
            for (int mi = 0; mi < 4; mi++)
                #pragma unroll
                for (int np = 0; np < 2; np++) {
                    mma_f16(acc[mi][np * 2 + 0], af[mi], bf[np][0], bf[np][1]);
                    mma_f16(acc[mi][np * 2 + 1], af[mi], bf[np][2], bf[np][3]);
                }
        }
    }

    #pragma unroll
    for (int mi = 0; mi < 4; mi++) {
        #pragma unroll
        for (int r2 = 0; r2 < 2; r2++) {
            const int m = mBase + wr * 64 + mi * 16 + g + r2 * 8;
            #pragma unroll
            for (int ni = 0; ni < 4; ni++) {
                const int n = nBase + wc * 32 + ni * 8 + 2 * t4;
                if (FUSED) {
                    const int which = n >> 11;        // 0=Q 1=K 2=V
                    const int n2 = n & (H_ - 1);
                    const float* bias = (which == 0) ? b0v : (which == 1) ? b1v : b2v;
                    __half* dst = (which == 0) ? o0 : (which == 1) ? o1 : o2;
                    const int b = m >> 11;
                    const int s = m & (S_ - 1);
                    const int h = n2 >> 7;
                    const int d = n2 & (HD_ - 1);
                    uint32_t pv = packh2(acc[mi][ni][r2 * 2 + 0] + bias[n2],
                                         acc[mi][ni][r2 * 2 + 1] + bias[n2 + 1]);
                    *(uint32_t*)&dst[(((size_t)(b * NH_ + h)) * S_ + s) * HD_ + d] = pv;
                } else {
                    float2 v;
                    v.x = acc[mi][ni][r2 * 2 + 0] + b0v[n];
                    v.y = acc[mi][ni][r2 * 2 + 1] + b0v[n + 1];
                    *(float2*)&of[(size_t)m * H_ + n] = v;
                }
            }
        }
    }
}

// ---------------------------------------------------------------------------
// fp16 flash attention, BKT=64. 8 warps x 16 rows, full N=64 / d=128 per warp.
// Per 64 K-cols: 2 syncs (was 4), half the O-rescales/softmax bookkeeping,
// 8 fewer Q ldmatrix. Single-buffered K/V, 2 CTAs/SM.
// ---------------------------------------------------------------------------
#define AT_BK   64
#define AQ_ROWB 272
#define AT_SMEM (128 * AQ_ROWB + 2 * AT_BK * AQ_ROWB + AT_BK * 4)   // 69888 B

__global__ __launch_bounds__(256, 2)
void attn_h(const __half* __restrict__ Q, const __half* __restrict__ K,
            const __half* __restrict__ V, const float* __restrict__ mask,
            __half* __restrict__ out)
{
    extern __shared__ char smc[];
    char* Qs = smc;                         // 128 x 272 B
    char* Ks = Qs + 128 * AQ_ROWB;          // 64 x 272 B
    char* Vs = Ks + AT_BK * AQ_ROWB;        // 64 x 272 B
    float* msk = (float*)(Vs + AT_BK * AQ_ROWB);   // 64 floats
    const uint32_t qbase = smem_u32(Qs);
    const uint32_t kbase = smem_u32(Ks);
    const uint32_t vbase = smem_u32(Vs);

    const int tid = threadIdx.x;
    const int w = tid >> 5, lane = tid & 31, g = lane >> 2, t4 = lane & 3;
    const int bh = blockIdx.y;
    const int b  = bh >> 4;
    const int q0 = blockIdx.x * 128;

    const __half* Qg = Q + ((size_t)bh * S_ + q0) * HD_;
    const __half* Kg = K + (size_t)bh * S_ * HD_;
    const __half* Vg = V + (size_t)bh * S_ * HD_;
    const float* maskg = mask + (size_t)b * S_;

    // Q tile: 128 rows x 256 B
    #pragma unroll
    for (int i = 0; i < 8; i++) {
        int id = tid + i * 256;
        int r = id >> 4, c = id & 15;
        cp16(Qs + r * AQ_ROWB + c * 16, Qg + (size_t)r * HD_ + c * 8);
    }
    auto loadKV = [&](int kb0) {
        #pragma unroll
        for (int i = 0; i < 4; i++) {
            int id = tid + i * 256;
            int r = id >> 4, c = id & 15;
            cp16(Ks + r * AQ_ROWB + c * 16, Kg + (size_t)(kb0 + r) * HD_ + c * 8);
            cp16(Vs + r * AQ_ROWB + c * 16, Vg + (size_t)(kb0 + r) * HD_ + c * 8);
        }
        if (tid < AT_BK) msk[tid] = maskg[kb0 + tid];
    };
    loadKV(0);
    cp_commit();
    cp_wait<0>();
    __syncthreads();

    float O[16][4];
    #pragma unroll
    for (int nt = 0; nt < 16; nt++)
        #pragma unroll
        for (int c = 0; c < 4; c++) O[nt][c] = 0.f;
    float m_lo = -1e30f, m_hi = -1e30f, l_lo = 0.f, l_hi = 0.f;

    const float scale = 0.08838834764831845f;   // 1/sqrt(128)
    const int nIter = S_ / AT_BK;               // 32

    const int aRow = (lane & 15);
    const int aChunk = (lane >> 4) << 4;
    const int li = lane >> 3;
    const int bRowOff = ((li >> 1) << 3) + (lane & 7);
    const int bChunk = (li & 1) << 4;
    const uint32_t qaddr0 = qbase + (w * 16 + aRow) * AQ_ROWB + aChunk;

    for (int kt = 0; kt < nIter; kt++) {
        // ---- S = Q @ K^T (16x64 per warp), 8 k16 steps ----
        float sacc[8][4] = {};
        #pragma unroll
        for (int k16 = 0; k16 < 8; k16++) {
            uint32_t af[4], bf[4][4];
            ldmx4(af, qaddr0 + k16 * 32);
            #pragma unroll
            for (int np = 0; np < 4; np++)
                ldmx4(bf[np], kbase + (np * 16 + bRowOff) * AQ_ROWB
                              + bChunk + k16 * 32);
            #pragma unroll
            for (int np = 0; np < 4; np++) {
                mma_f16(sacc[np * 2 + 0], af, bf[np][0], bf[np][1]);
                mma_f16(sacc[np * 2 + 1], af, bf[np][2], bf[np][3]);
            }
        }

        // ---- scale + mask ----
        #pragma unroll
        for (int ni = 0; ni < 8; ni++)
            #pragma unroll
            for (int c = 0; c < 4; c++) {
                const int col = ni * 8 + 2 * t4 + (c & 1);
                sacc[ni][c] = sacc[ni][c] * scale + msk[col];
            }

        // ---- in-warp softmax (rows g, g+8; quad reduce over t4) ----
        float rm_lo = -1e30f, rm_hi = -1e30f;
        #pragma unroll
        for (int ni = 0; ni < 8; ni++) {
            rm_lo = fmaxf(rm_lo, fmaxf(sacc[ni][0], sacc[ni][1]));
            rm_hi = fmaxf(rm_hi, fmaxf(sacc[ni][2], sacc[ni][3]));
        }
        rm_lo = fmaxf(rm_lo, __shfl_xor_sync(0xffffffffu, rm_lo, 1));
        rm_lo = fmaxf(rm_lo, __shfl_xor_sync(0xffffffffu, rm_lo, 2));
        rm_hi = fmaxf(rm_hi, __shfl_xor_sync(0xffffffffu, rm_hi, 1));
        rm_hi = fmaxf(rm_hi, __shfl_xor_sync(0xffffffffu, rm_hi, 2));

        const float mn_lo = fmaxf(m_lo, rm_lo);
        const float mn_hi = fmaxf(m_hi, rm_hi);
        const float al_lo = __expf(m_lo - mn_lo);
        const float al_hi = __expf(m_hi - mn_hi);
        m_lo = mn_lo;
        m_hi = mn_hi;

        float sum_lo = 0.f, sum_hi = 0.f;
        #pragma unroll
        for (int ni = 0; ni < 8; ni++) {
            sacc[ni][0] = __expf(sacc[ni][0] - mn_lo);
            sacc[ni][1] = __expf(sacc[ni][1] - mn_lo);
            sacc[ni][2] = __expf(sacc[ni][2] - mn_hi);
            sacc[ni][3] = __expf(sacc[ni][3] - mn_hi);
            sum_lo += sacc[ni][0] + sacc[ni][1];
            sum_hi += sacc[ni][2] + sacc[ni][3];
        }
        sum_lo += __shfl_xor_sync(0xffffffffu, sum_lo, 1);
        sum_lo += __shfl_xor_sync(0xffffffffu, sum_lo, 2);
        sum_hi += __shfl_xor_sync(0xffffffffu, sum_hi, 1);
        sum_hi += __shfl_xor_sync(0xffffffffu, sum_hi, 2);
        l_lo = l_lo * al_lo + sum_lo;
        l_hi = l_hi * al_hi + sum_hi;

        #pragma unroll
        for (int nt = 0; nt < 16; nt++) {
            O[nt][0] *= al_lo;  O[nt][1] *= al_lo;
            O[nt][2] *= al_hi;  O[nt][3] *= al_hi;
        }

        // ---- O += P @ V : P packed straight from S accumulators ----
        #pragma unroll
        for (int kb = 0; kb < 4; kb++) {
            uint32_t af[4];
            af[0] = packh2(sacc[2 * kb][0],     sacc[2 * kb][1]);
            af[1] = packh2(sacc[2 * kb][2],     sacc[2 * kb][3]);
            af[2] = packh2(sacc[2 * kb + 1][0], sacc[2 * kb + 1][1]);
            af[3] = packh2(sacc[2 * kb + 1][2], sacc[2 * kb + 1][3]);
            #pragma unroll
            for (int t = 0; t < 8; t++) {
                uint32_t bf[4];
                ldmx4t(bf, vbase + (kb * 16 + aRow) * AQ_ROWB
                           + (2 * t) * 16 + aChunk);
                mma_f16(O[2 * t + 0], af, bf[0], bf[1]);
                mma_f16(O[2 * t + 1], af, bf[2], bf[3]);
            }
        }

        __syncthreads();
        if (kt + 1 < nIter) {
            loadKV((kt + 1) * AT_BK);
            cp_commit();
            cp_wait<0>();
        }
        __syncthreads();
    }

    // ---- finalize ----
    const int h = bh & (NH_ - 1);
    const float inv_lo = 1.f / l_lo;
    const float inv_hi = 1.f / l_hi;
    const int q_lo = q0 + w * 16 + g;
    __half* dst_lo = out + ((size_t)b * S_ + q_lo) * H_ + h * HD_;
    __half* dst_hi = dst_lo + (size_t)8 * H_;
    #pragma unroll
    for (int nt = 0; nt < 16; nt++) {
        const int col = nt * 8 + 2 * t4;
        *(uint32_t*)&dst_lo[col] = packh2(O[nt][0] * inv_lo, O[nt][1] * inv_lo);
        *(uint32_t*)&dst_hi[col] = packh2(O[nt][2] * inv_hi, O[nt][3] * inv_hi);
    }
}

// ---------------------------------------------------------------------------
// Launch
// ---------------------------------------------------------------------------
extern "C" void kernel_launch(void* const* d_in, const int* in_sizes, int n_in,
                              void* d_out, int out_size)
{
    const float* x    = (const float*)d_in[0];
    const float* mask = (const float*)d_in[1];
    const float* Wq   = (const float*)d_in[2];
    const float* bq   = (const float*)d_in[3];
    const float* Wk   = (const float*)d_in[4];
    const float* bk   = (const float*)d_in[5];
    const float* Wv   = (const float*)d_in[6];
    const float* bv   = (const float*)d_in[7];
    const float* Wo   = (const float*)d_in[8];
    const float* bo   = (const float*)d_in[9];
    float* out = (float*)d_out;

    __half *q, *k, *v, *attn, *xh, *wt;
    cudaGetSymbolAddress((void**)&q,    g_q);
    cudaGetSymbolAddress((void**)&k,    g_k);
    cudaGetSymbolAddress((void**)&v,    g_v);
    cudaGetSymbolAddress((void**)&attn, g_attn);
    cudaGetSymbolAddress((void**)&xh,   g_xh);
    cudaGetSymbolAddress((void**)&wt,   g_wt);

    cudaFuncSetAttribute(gemm_h<true>,
                         cudaFuncAttributeMaxDynamicSharedMemorySize, GH_SMEM);
    cudaFuncSetAttribute(gemm_h<false>,
                         cudaFuncAttributeMaxDynamicSharedMemorySize, GH_SMEM);
    cudaFuncSetAttribute(attn_h,
                         cudaFuncAttributeMaxDynamicSharedMemorySize, AT_SMEM);

    // Prep: x -> fp16; all 4 weights transposed in one launch
    const int nx4 = MTOT * H_ / 4;
    halfcast<<<(nx4 + 255) / 256, 256>>>(x, xh, nx4);
    transpose_half4<<<dim3(H_ / 32, H_ / 32, 4), dim3(32, 8)>>>(Wq, Wk, Wv, Wo, wt);

    const size_t wsz = (size_t)H_ * H_;

    // Fused QKV projection (N = 3*2048)
    gemm_h<true><<<dim3(3 * H_ / 128, MTOT / 128), 256, GH_SMEM>>>(
        xh, wt, bq, bk, bv, q, k, v, nullptr);

    attn_h<<<dim3(S_ / 128, B_ * NH_), 256, AT_SMEM>>>(q, k, v, mask, attn);

    // Out projection (fp32 output)
    gemm_h<false><<<dim3(H_ / 128, MTOT / 128), 256, GH_SMEM>>>(
        attn, wt + 3 * wsz, bo, nullptr, nullptr,
        nullptr, nullptr, nullptr, out);
}